// round 15
// baseline (speedup 1.0000x reference)
#include <cuda_runtime.h>
#include <cuda_fp16.h>
#include <cstdint>
#include <cstddef>

#define Bz 128
#define Ez 512
#define Dz 512
#define Vz 275
#define Pz 576
#define Tz 300
#define TM1 299
#define EP (Ez*Pz)
#define GRID 256
#define NTHR 256
#define DSMEM 86016    // 12288 scratch + 73728 ctx pipe (score 65536, D 73984 fit)

// ---------------- scratch (device globals; no allocs allowed) ----------------
__device__ __align__(16) __half g_Ws[(size_t)Bz*Pz*Dz];     // fp16 flat@W_w + W_b
__device__ __align__(16) __half g_featsh[(size_t)Bz*EP];    // fp16 feats
__device__ __align__(16) float g_fcwT[Vz*Dz];               // fc weights [V][D]
__device__ __align__(16) float g_embW[Vz*2048];             // emb @ wih[:, :512]^T
__device__ __align__(16) float g_mean[Bz*Ez];
__device__ __align__(16) float g_h[2][Bz*Dz];
__device__ __align__(16) float g_c[2][Bz*Dz];
__device__ __align__(16) float g_p1[16][Bz*1024];           // (hU|gate) split-K partials
__device__ __align__(16) float g_e[Bz*Pz];                  // attention scores
__device__ __align__(16) float g_gate[Bz*2048];             // LSTM gates (mma output)
__device__ __align__(16) __half g_A2h_hi[Bz*1024];          // [ctx | h] fp16 hi
__device__ __align__(16) __half g_A2h_lo[Bz*1024];          // residual lo
__device__ __align__(16) __half g_W2h_hi[(size_t)2048*1024];// [wih(ctx part) | whh] hi
__device__ __align__(16) __half g_W2h_lo[(size_t)2048*1024];// residual lo
__device__ unsigned g_sf[GRID];                             // pair score-done flags

// ---------------- software grid barrier --------------------------------------
__device__ unsigned g_bar_count;
__device__ volatile unsigned g_bar_gen;

__device__ __forceinline__ void gridsync() {
    __syncthreads();
    if (threadIdx.x == 0) {
        __threadfence();
        unsigned gen = g_bar_gen;
        if (atomicAdd(&g_bar_count, 1u) == GRID - 1) {
            g_bar_count = 0;
            __threadfence();
            g_bar_gen = gen + 1;
        } else {
            while (g_bar_gen == gen) {}
        }
        __threadfence();
    }
    __syncthreads();
}

// ---------------- async copy / mma helpers -----------------------------------
__device__ __forceinline__ void cp16(void* dst_smem, const void* src) {
    unsigned d = (unsigned)__cvta_generic_to_shared(dst_smem);
    asm volatile("cp.async.cg.shared.global [%0], [%1], 16;"
                 :: "r"(d), "l"(src) : "memory");
}
#define CP_COMMIT() asm volatile("cp.async.commit_group;" ::: "memory")
#define CP_WAIT(n)  asm volatile("cp.async.wait_group %0;" :: "n"(n) : "memory")
__device__ __forceinline__ void cp_wait_dyn(int n) {
    if (n >= 3)      { CP_WAIT(3); }
    else if (n == 2) { CP_WAIT(2); }
    else if (n == 1) { CP_WAIT(1); }
    else             { CP_WAIT(0); }
}

__device__ __forceinline__ void ldsm4(unsigned& r0, unsigned& r1, unsigned& r2,
                                      unsigned& r3, const void* p) {
    unsigned a = (unsigned)__cvta_generic_to_shared(p);
    asm volatile("ldmatrix.sync.aligned.m8n8.x4.shared.b16 {%0,%1,%2,%3}, [%4];"
                 : "=r"(r0), "=r"(r1), "=r"(r2), "=r"(r3) : "r"(a));
}
__device__ __forceinline__ void ldsm2(unsigned& r0, unsigned& r1, const void* p) {
    unsigned a = (unsigned)__cvta_generic_to_shared(p);
    asm volatile("ldmatrix.sync.aligned.m8n8.x2.shared.b16 {%0,%1}, [%2];"
                 : "=r"(r0), "=r"(r1) : "r"(a));
}
__device__ __forceinline__ void mma16816(float& c0, float& c1, float& c2, float& c3,
                                         unsigned a0, unsigned a1, unsigned a2,
                                         unsigned a3, unsigned b0, unsigned b1) {
    asm volatile("mma.sync.aligned.m16n8k16.row.col.f32.f16.f16.f32 "
                 "{%0,%1,%2,%3}, {%4,%5,%6,%7}, {%8,%9}, {%0,%1,%2,%3};"
                 : "+f"(c0), "+f"(c1), "+f"(c2), "+f"(c3)
                 : "r"(a0), "r"(a1), "r"(a2), "r"(a3), "r"(b0), "r"(b1));
}

// ---------------- activation helpers -----------------------------------------
__device__ __forceinline__ __half2 tanh2(__half2 x) {
    unsigned xi = *reinterpret_cast<unsigned*>(&x);
    unsigned yi;
    asm("tanh.approx.f16x2 %0, %1;" : "=r"(yi) : "r"(xi));
    return *reinterpret_cast<__half2*>(&yi);
}
__device__ __forceinline__ float fast_tanh(float x) {
    float t = fminf(fmaxf(x * 2.885390081777927f, -252.0f), 252.0f);
    float z; asm("ex2.approx.f32 %0, %1;" : "=f"(z) : "f"(t));
    float den = z + 1.0f;
    float r; asm("rcp.approx.f32 %0, %1;" : "=f"(r) : "f"(den));
    return (z - 1.0f) * r;
}
__device__ __forceinline__ float fast_sigmoid(float x) {
    float t = fminf(fmaxf(x * -1.4426950408889634f, -252.0f), 252.0f);
    float z; asm("ex2.approx.f32 %0, %1;" : "=f"(z) : "f"(t));
    float den = z + 1.0f;
    float r; asm("rcp.approx.f32 %0, %1;" : "=f"(r) : "f"(den));
    return r;
}

// ======= launch 1: mean + fcwT + embW + W2h(hi/lo) + dec_len =================
__global__ void prep_misc_kernel(const float* __restrict__ feats,
                                 const float* __restrict__ fcw,
                                 const float* __restrict__ emb,
                                 const float* __restrict__ wih,
                                 const float* __restrict__ whh,
                                 const int* __restrict__ lengths,
                                 float* __restrict__ dec) {
    __shared__ float er[512];
    int bx = blockIdx.x, tid = threadIdx.x;
    if (bx < 8192) {                                  // mean over P
        int warp = tid >> 5, lane = tid & 31;
        int idx = bx * 8 + warp;
        int b = idx >> 9, e = idx & 511;
        const float* src = feats + (size_t)b * EP + (size_t)e * Pz;
        float acc = 0.f;
        #pragma unroll
        for (int k = 0; k < 18; k++) acc += src[lane + k * 32];
        #pragma unroll
        for (int o = 16; o; o >>= 1) acc += __shfl_down_sync(0xffffffffu, acc, o);
        if (lane == 0) g_mean[idx] = acc * (1.0f / 576.0f);
    } else if (bx < 8742) {                           // fcw transpose
        int idx = (bx - 8192) * 256 + tid;
        int v = idx >> 9, d = idx & 511;
        g_fcwT[v * 512 + d] = fcw[d * Vz + v];
    } else if (bx < 9017) {                           // embW: one token per block
        int v = bx - 8742;
        for (int i = tid; i < 512; i += 256) er[i] = emb[v * 512 + i];
        __syncthreads();
        for (int j = tid; j < 2048; j += 256) {
            const float* wr = wih + (size_t)j * 1024;
            float a0 = 0.f, a1 = 0.f, a2 = 0.f, a3 = 0.f;
            #pragma unroll 8
            for (int k = 0; k < 512; k += 4) {
                float4 w = *reinterpret_cast<const float4*>(wr + k);
                float4 e4 = *reinterpret_cast<const float4*>(&er[k]);
                a0 = fmaf(w.x, e4.x, a0);
                a1 = fmaf(w.y, e4.y, a1);
                a2 = fmaf(w.z, e4.z, a2);
                a3 = fmaf(w.w, e4.w, a3);
            }
            g_embW[v * 2048 + j] = (a0 + a1) + (a2 + a3);
        }
    } else if (bx < 17209) {                          // W2h hi/lo
        int idx = (bx - 9017) * 256 + tid;            // < 2048*1024
        int j = idx >> 10, k = idx & 1023;
        float w = (k < 512) ? wih[(size_t)j * 1024 + 512 + k]
                            : whh[(size_t)j * 512 + (k - 512)];
        __half hi = __float2half_rn(w);
        g_W2h_hi[idx] = hi;
        g_W2h_lo[idx] = __float2half_rn(w - __half2float(hi));
    } else {                                          // dec_len
        if (tid < Bz) dec[tid] = (float)(lengths[tid] - 1);
    }
}

// ======= launch 2: f2h + init h0/c0 gemm (+ h0 fp16 hi/lo) ===================
__global__ void prep2_kernel(const float* __restrict__ feats,
                             const float* __restrict__ W1,
                             const float* __restrict__ W2,
                             const float* __restrict__ b1,
                             const float* __restrict__ b2) {
    int bx = blockIdx.x, tid = threadIdx.x;
    if (bx < 18432) {
        size_t i = ((size_t)bx * 256 + tid) * 8;
        float4 v0 = *reinterpret_cast<const float4*>(feats + i);
        float4 v1 = *reinterpret_cast<const float4*>(feats + i + 4);
        __half2 h0 = __floats2half2_rn(v0.x, v0.y);
        __half2 h1 = __floats2half2_rn(v0.z, v0.w);
        __half2 h2 = __floats2half2_rn(v1.x, v1.y);
        __half2 h3 = __floats2half2_rn(v1.z, v1.w);
        uint4 o;
        o.x = *reinterpret_cast<unsigned*>(&h0);
        o.y = *reinterpret_cast<unsigned*>(&h1);
        o.z = *reinterpret_cast<unsigned*>(&h2);
        o.w = *reinterpret_cast<unsigned*>(&h3);
        *reinterpret_cast<uint4*>(g_featsh + i) = o;
        return;
    }
    int jt = bx - 18432;
    const float* W = (jt < 8) ? W1 : W2;
    const float* bias = (jt < 8) ? b1 : b2;
    int wj0 = ((jt < 8) ? jt : jt - 8) * 64;
    __shared__ float As[8][128];
    __shared__ float Bs[8][64];
    int tx = tid & 15, ty = tid >> 4;
    float acc[8][4] = {};
    for (int kk = 0; kk < 512; kk += 8) {
        {
            int b = tid >> 1, r4 = (tid & 1) * 4;
            float4 v = *reinterpret_cast<const float4*>(&g_mean[b * 512 + kk + r4]);
            As[r4 + 0][b] = v.x; As[r4 + 1][b] = v.y; As[r4 + 2][b] = v.z; As[r4 + 3][b] = v.w;
        }
        if (tid < 128) {
            int j4 = (tid & 15) * 4, r = tid >> 4;
            float4 v = *reinterpret_cast<const float4*>(&W[(kk + r) * 512 + wj0 + j4]);
            Bs[r][j4 + 0] = v.x; Bs[r][j4 + 1] = v.y; Bs[r][j4 + 2] = v.z; Bs[r][j4 + 3] = v.w;
        }
        __syncthreads();
        #pragma unroll
        for (int r = 0; r < 8; r++) {
            float4 w4 = *reinterpret_cast<const float4*>(&Bs[r][tx * 4]);
            float4 a0 = *reinterpret_cast<const float4*>(&As[r][ty * 8]);
            float4 a1 = *reinterpret_cast<const float4*>(&As[r][ty * 8 + 4]);
            float a[8] = {a0.x, a0.y, a0.z, a0.w, a1.x, a1.y, a1.z, a1.w};
            float w[4] = {w4.x, w4.y, w4.z, w4.w};
            #pragma unroll
            for (int i = 0; i < 8; i++)
                #pragma unroll
                for (int jj = 0; jj < 4; jj++)
                    acc[i][jj] = fmaf(a[i], w[jj], acc[i][jj]);
        }
        __syncthreads();
    }
    float* dst = (jt < 8) ? g_h[0] : g_c[0];
    int j = wj0 + tx * 4;
    float4 bb = *reinterpret_cast<const float4*>(&bias[j]);
    #pragma unroll
    for (int i = 0; i < 8; i++) {
        int b = ty * 8 + i;
        float4 v = {acc[i][0] + bb.x, acc[i][1] + bb.y, acc[i][2] + bb.z, acc[i][3] + bb.w};
        *reinterpret_cast<float4*>(&dst[b * 512 + j]) = v;
        if (jt < 8) {
            #pragma unroll
            for (int q = 0; q < 4; q++) {
                float x = (&v.x)[q];
                __half hi = __float2half_rn(x);
                g_A2h_hi[b * 1024 + 512 + j + q] = hi;
                g_A2h_lo[b * 1024 + 512 + j + q] = __float2half_rn(x - __half2float(hi));
            }
        }
    }
}

// ======= launch 3: Ws precompute (fp16) ======================================
__global__ void ws_gemm_kernel(const float* __restrict__ feats,
                               const float* __restrict__ Ww,
                               const float* __restrict__ Wb) {
    int b = blockIdx.z;
    int p0 = blockIdx.x * 64;
    int d0 = blockIdx.y * 64;
    __shared__ float As[8][64];
    __shared__ float Bs[8][64];
    int tid = threadIdx.x, tx = tid & 15, ty = tid >> 4;
    float acc[4][4] = {};
    const float* fb = feats + (size_t)b * EP;
    for (int kk = 0; kk < 512; kk += 8) {
        if (tid < 128) {
            int p4 = (tid & 15) * 4, r = tid >> 4;
            float4 v = *reinterpret_cast<const float4*>(&fb[(size_t)(kk + r) * Pz + p0 + p4]);
            As[r][p4 + 0] = v.x; As[r][p4 + 1] = v.y; As[r][p4 + 2] = v.z; As[r][p4 + 3] = v.w;
        } else {
            int t2 = tid - 128;
            int d4 = (t2 & 15) * 4, r = t2 >> 4;
            float4 v = *reinterpret_cast<const float4*>(&Ww[(kk + r) * 512 + d0 + d4]);
            Bs[r][d4 + 0] = v.x; Bs[r][d4 + 1] = v.y; Bs[r][d4 + 2] = v.z; Bs[r][d4 + 3] = v.w;
        }
        __syncthreads();
        #pragma unroll
        for (int r = 0; r < 8; r++) {
            float4 a4 = *reinterpret_cast<const float4*>(&As[r][ty * 4]);
            float4 w4 = *reinterpret_cast<const float4*>(&Bs[r][tx * 4]);
            float a[4] = {a4.x, a4.y, a4.z, a4.w};
            float w[4] = {w4.x, w4.y, w4.z, w4.w};
            #pragma unroll
            for (int i = 0; i < 4; i++)
                #pragma unroll
                for (int jj = 0; jj < 4; jj++)
                    acc[i][jj] = fmaf(a[i], w[jj], acc[i][jj]);
        }
        __syncthreads();
    }
    float4 wb4 = *reinterpret_cast<const float4*>(&Wb[d0 + tx * 4]);
    #pragma unroll
    for (int i = 0; i < 4; i++) {
        size_t row = (size_t)(b * Pz + p0 + ty * 4 + i);
        __half2 h01 = __floats2half2_rn(acc[i][0] + wb4.x, acc[i][1] + wb4.y);
        __half2 h23 = __floats2half2_rn(acc[i][2] + wb4.z, acc[i][3] + wb4.w);
        uint2 u;
        u.x = *reinterpret_cast<unsigned*>(&h01);
        u.y = *reinterpret_cast<unsigned*>(&h23);
        *reinterpret_cast<uint2*>(&g_Ws[row * 512 + d0 + tx * 4]) = u;
    }
}

// ============================================================================
//  launch 4 (PROFILED): persistent decode, 256 blocks x 256 thr, 2 blocks/SM
//  pair (2b, 2b+1) splits batch b's BC and E; D = 8 j-cols per block
// ============================================================================
__global__ void __launch_bounds__(NTHR, 2) decode_kernel(
    const float* __restrict__ Uw,  const float* __restrict__ Ub,
    const float* __restrict__ vw,  const float* __restrict__ vb,
    const float* __restrict__ fbw, const float* __restrict__ fbb,
    const int*   __restrict__ captions,
    const int*   __restrict__ lengths,
    const float* __restrict__ bih, const float* __restrict__ bhh,
    const float* __restrict__ fcb,
    float* __restrict__ preds_out, float* __restrict__ alphas_out)
{
    extern __shared__ __align__(16) char dyns[];
    float* smf = reinterpret_cast<float*>(dyns);
    const int bx = blockIdx.x, tid = threadIdx.x;
    const int wid = tid >> 5, lane = tid & 31;
    const int bb_ = bx >> 1, half = bx & 1;

    for (int t = 0; t < TM1; t++) {
        const int cur = t & 1;
        const float* h = g_h[cur];

        // ------------- Phase A: (hU | gate-raw) partials, 16 jt x 16 kc ------
        {
            if (t == 0 && tid == 0) g_sf[bx] = 0;      // reset pair flags
            int jt = bx & 15, kc = bx >> 4;
            const float* W = (jt < 8) ? Uw : fbw;
            int wj0 = ((jt < 8) ? jt : jt - 8) * 64;
            int k0 = kc * 32;
            float* As = smf;             // [32][128]
            float* Bs = smf + 4096;      // [32][64]
            {
                int b = tid >> 1, h16 = (tid & 1) * 16;
                #pragma unroll
                for (int q = 0; q < 4; q++) {
                    float4 v = *reinterpret_cast<const float4*>(&h[b * 512 + k0 + h16 + q * 4]);
                    As[(h16 + q * 4 + 0) * 128 + b] = v.x;
                    As[(h16 + q * 4 + 1) * 128 + b] = v.y;
                    As[(h16 + q * 4 + 2) * 128 + b] = v.z;
                    As[(h16 + q * 4 + 3) * 128 + b] = v.w;
                }
            }
            {
                int r = tid >> 3, j8 = (tid & 7) * 8;
                float4 v0 = *reinterpret_cast<const float4*>(&W[(k0 + r) * 512 + wj0 + j8]);
                float4 v1 = *reinterpret_cast<const float4*>(&W[(k0 + r) * 512 + wj0 + j8 + 4]);
                *reinterpret_cast<float4*>(&Bs[r * 64 + j8]) = v0;
                *reinterpret_cast<float4*>(&Bs[r * 64 + j8 + 4]) = v1;
            }
            __syncthreads();
            int tx = tid & 15, ty = tid >> 4;
            float acc[8][4] = {};
            #pragma unroll
            for (int r = 0; r < 32; r++) {
                float4 w4 = *reinterpret_cast<const float4*>(&Bs[r * 64 + tx * 4]);
                float4 a0 = *reinterpret_cast<const float4*>(&As[r * 128 + ty * 8]);
                float4 a1 = *reinterpret_cast<const float4*>(&As[r * 128 + ty * 8 + 4]);
                float a[8] = {a0.x, a0.y, a0.z, a0.w, a1.x, a1.y, a1.z, a1.w};
                float w[4] = {w4.x, w4.y, w4.z, w4.w};
                #pragma unroll
                for (int i = 0; i < 8; i++)
                    #pragma unroll
                    for (int jj = 0; jj < 4; jj++)
                        acc[i][jj] = fmaf(a[i], w[jj], acc[i][jj]);
            }
            float* pOut = g_p1[kc];
            int jg = jt * 64 + tx * 4;
            #pragma unroll
            for (int i = 0; i < 8; i++) {
                int b = ty * 8 + i;
                float4 v = {acc[i][0], acc[i][1], acc[i][2], acc[i][3]};
                *reinterpret_cast<float4*>(&pOut[b * 1024 + jg]) = v;
            }
        }
        gridsync();

        // ------------- Phase BC: attention + softmax + ctx (pair splits b) ---
        {
            const int b = bb_;
            float* hU = smf;             // [0, 512)
            float* gs = smf + 512;       // [512, 1024)
            float* es = smf + 1024;      // [1024, 1600)
            float* red = smf + 1600;     // [1600, 1856)
            __half2* hU2s = reinterpret_cast<__half2*>(smf + 1856);
            __half2* vs2s = reinterpret_cast<__half2*>(smf + 2112);
            __half2* es2s = reinterpret_cast<__half2*>(smf + 2368);  // ..2656
            __half* pipe = reinterpret_cast<__half*>(dyns + 12288);
            for (int d = tid; d < 512; d += NTHR) {
                float s = Ub[d], g = fbb[d];
                #pragma unroll
                for (int kc = 0; kc < 16; kc++) {
                    s += g_p1[kc][b * 1024 + d];
                    g += g_p1[kc][b * 1024 + 512 + d];
                }
                hU[d] = s; gs[d] = fast_sigmoid(g);
            }
            __syncthreads();
            hU2s[tid] = __floats2half2_rn(hU[2 * tid], hU[2 * tid + 1]);
            vs2s[tid] = __floats2half2_rn(vw[2 * tid], vw[2 * tid + 1]);
            __syncthreads();
            float vb0 = vb[0];
            // ====== score: this block's 288 rows, 8 warps x 2 rows x 18 stages
            {
                const __half* wsb = g_Ws + (size_t)b * (Pz * 512);
                int pbase = half * 288;
                __half* wpipe = pipe + wid * 4096;
                #pragma unroll
                for (int s = 0; s < 4; s++) {
                    int p0 = pbase + wid * 2 + s * 16;
                    const __half* src = wsb + (size_t)p0 * 512;
                    __half* dst = wpipe + (s & 3) * 1024;
                    #pragma unroll
                    for (int q = 0; q < 4; q++) {
                        int cc = lane * 4 + q;
                        int r = cc >> 6, off = (cc & 63) * 8;
                        cp16(dst + r * 512 + off, src + (size_t)r * 512 + off);
                    }
                    CP_COMMIT();
                }
                for (int s = 0; s < 18; s++) {
                    cp_wait_dyn(17 - s < 3 ? 17 - s : 3);
                    __syncwarp();
                    const __half2* r0 = reinterpret_cast<const __half2*>(wpipe + (s & 3) * 1024);
                    const __half2* r1 = r0 + 256;
                    float a0 = 0.f, a1 = 0.f;
                    #pragma unroll
                    for (int k = 0; k < 2; k++) {
                        int d2 = lane * 4 + k * 128;
                        uint4 u0 = *reinterpret_cast<const uint4*>(r0 + d2);
                        uint4 u1 = *reinterpret_cast<const uint4*>(r1 + d2);
                        uint4 hu = *reinterpret_cast<const uint4*>(hU2s + d2);
                        uint4 vv = *reinterpret_cast<const uint4*>(vs2s + d2);
                        __half2 acc0 = __float2half2_rn(0.f);
                        __half2 acc1 = acc0;
                        #pragma unroll
                        for (int j = 0; j < 4; j++) {
                            __half2 hj = *reinterpret_cast<__half2*>(&(&hu.x)[j]);
                            __half2 vj = *reinterpret_cast<__half2*>(&(&vv.x)[j]);
                            __half2 w0 = *reinterpret_cast<__half2*>(&(&u0.x)[j]);
                            __half2 w1 = *reinterpret_cast<__half2*>(&(&u1.x)[j]);
                            acc0 = __hfma2(vj, tanh2(__hadd2(w0, hj)), acc0);
                            acc1 = __hfma2(vj, tanh2(__hadd2(w1, hj)), acc1);
                        }
                        float2 f0 = __half22float2(acc0);
                        float2 f1 = __half22float2(acc1);
                        a0 += f0.x + f0.y;
                        a1 += f1.x + f1.y;
                    }
                    #pragma unroll
                    for (int o = 16; o; o >>= 1) {
                        a0 += __shfl_down_sync(0xffffffffu, a0, o);
                        a1 += __shfl_down_sync(0xffffffffu, a1, o);
                    }
                    int p = pbase + wid * 2 + s * 16;
                    if (lane == 0) {
                        g_e[b * Pz + p]     = a0 + vb0;
                        g_e[b * Pz + p + 1] = a1 + vb0;
                    }
                    __syncwarp();
                    if (s + 4 < 18) {
                        int pn = pbase + wid * 2 + (s + 4) * 16;
                        const __half* src = wsb + (size_t)pn * 512;
                        __half* dst = wpipe + (s & 3) * 1024;
                        #pragma unroll
                        for (int q = 0; q < 4; q++) {
                            int cc = lane * 4 + q;
                            int r = cc >> 6, off = (cc & 63) * 8;
                            cp16(dst + r * 512 + off, src + (size_t)r * 512 + off);
                        }
                        CP_COMMIT();
                    }
                }
            }
            // ---- pair sync: both halves' scores visible
            __syncthreads();
            if (tid == 0) {
                __threadfence();
                atomicExch(&g_sf[bx], (unsigned)(t + 1));
                while (atomicAdd(&g_sf[bx ^ 1], 0u) < (unsigned)(t + 1)) {}
            }
            __syncthreads();
            for (int p = tid; p < Pz; p += NTHR) es[p] = g_e[b * Pz + p];
            __syncthreads();
            // ---- softmax over 576 (redundant in both halves, deterministic)
            float lmax = -1e30f;
            for (int p = tid; p < Pz; p += NTHR) lmax = fmaxf(lmax, es[p]);
            red[tid] = lmax; __syncthreads();
            for (int o = 128; o; o >>= 1) {
                if (tid < o) red[tid] = fmaxf(red[tid], red[tid + o]);
                __syncthreads();
            }
            float mx = red[0]; __syncthreads();
            float ls = 0.f;
            for (int p = tid; p < Pz; p += NTHR) {
                float v = __expf(es[p] - mx);
                es[p] = v; ls += v;
            }
            red[tid] = ls; __syncthreads();
            for (int o = 128; o; o >>= 1) {
                if (tid < o) red[tid] += red[tid + o];
                __syncthreads();
            }
            float inv = 1.0f / red[0];
            float msk = ((lengths[b] - 1) > t) ? 1.0f : 0.0f;
            for (int p = tid; p < Pz; p += NTHR) {
                float a = es[p] * inv;
                es[p] = a;
                if ((p >= half * 288) && (p < half * 288 + 288))
                    alphas_out[((size_t)b * TM1 + t) * Pz + p] = a * msk;
            }
            __syncthreads();
            for (int i = tid; i < 288; i += NTHR)
                es2s[i] = __floats2half2_rn(es[2 * i], es[2 * i + 1]);
            __syncthreads();
            // ====== ctx: this block's 256 e-rows, 8 warps x 2 x 16 stages ====
            {
                const __half* fhb = g_featsh + (size_t)b * EP;
                int ebase = half * 256;
                __half* wpipe = pipe + wid * 4608;
                #pragma unroll
                for (int s = 0; s < 4; s++) {
                    int e0 = ebase + wid * 2 + s * 16;
                    const __half* src = fhb + (size_t)e0 * Pz;
                    __half* dst = wpipe + (s & 3) * 1152;
                    #pragma unroll
                    for (int q = 0; q < 5; q++) {
                        int cc = lane + q * 32;
                        if (cc < 144) {
                            int r = cc / 72, off = (cc % 72) * 8;
                            cp16(dst + r * 576 + off, src + (size_t)r * Pz + off);
                        }
                    }
                    CP_COMMIT();
                }
                for (int s = 0; s < 16; s++) {
                    cp_wait_dyn(15 - s < 3 ? 15 - s : 3);
                    __syncwarp();
                    const __half2* r0 = reinterpret_cast<const __half2*>(wpipe + (s & 3) * 1152);
                    const __half2* r1 = r0 + 288;
                    float a0 = 0.f, a1 = 0.f;
                    #pragma unroll
                    for (int k = 0; k < 2; k++) {
                        int d2 = lane * 4 + k * 128;
                        uint4 u0 = *reinterpret_cast<const uint4*>(r0 + d2);
                        uint4 u1 = *reinterpret_cast<const uint4*>(r1 + d2);
                        uint4 ev = *reinterpret_cast<const uint4*>(es2s + d2);
                        __half2 acc0 = __float2half2_rn(0.f);
                        __half2 acc1 = acc0;
                        #pragma unroll
                        for (int j = 0; j < 4; j++) {
                            __half2 ej = *reinterpret_cast<__half2*>(&(&ev.x)[j]);
                            __half2 w0 = *reinterpret_cast<__half2*>(&(&u0.x)[j]);
                            __half2 w1 = *reinterpret_cast<__half2*>(&(&u1.x)[j]);
                            acc0 = __hfma2(w0, ej, acc0);
                            acc1 = __hfma2(w1, ej, acc1);
                        }
                        float2 f0 = __half22float2(acc0);
                        float2 f1 = __half22float2(acc1);
                        a0 += f0.x + f0.y;
                        a1 += f1.x + f1.y;
                    }
                    if (lane < 8) {
                        int d2 = 256 + lane * 4;
                        uint4 u0 = *reinterpret_cast<const uint4*>(r0 + d2);
                        uint4 u1 = *reinterpret_cast<const uint4*>(r1 + d2);
                        uint4 ev = *reinterpret_cast<const uint4*>(es2s + d2);
                        __half2 acc0 = __float2half2_rn(0.f);
                        __half2 acc1 = acc0;
                        #pragma unroll
                        for (int j = 0; j < 4; j++) {
                            __half2 ej = *reinterpret_cast<__half2*>(&(&ev.x)[j]);
                            __half2 w0 = *reinterpret_cast<__half2*>(&(&u0.x)[j]);
                            __half2 w1 = *reinterpret_cast<__half2*>(&(&u1.x)[j]);
                            acc0 = __hfma2(w0, ej, acc0);
                            acc1 = __hfma2(w1, ej, acc1);
                        }
                        float2 f0 = __half22float2(acc0);
                        float2 f1 = __half22float2(acc1);
                        a0 += f0.x + f0.y;
                        a1 += f1.x + f1.y;
                    }
                    #pragma unroll
                    for (int o = 16; o; o >>= 1) {
                        a0 += __shfl_down_sync(0xffffffffu, a0, o);
                        a1 += __shfl_down_sync(0xffffffffu, a1, o);
                    }
                    int e = ebase + wid * 2 + s * 16;
                    if (lane == 0) {
                        float x0 = gs[e] * a0;
                        float x1 = gs[e + 1] * a1;
                        __half hi0 = __float2half_rn(x0);
                        __half hi1 = __float2half_rn(x1);
                        g_A2h_hi[b * 1024 + e]     = hi0;
                        g_A2h_hi[b * 1024 + e + 1] = hi1;
                        g_A2h_lo[b * 1024 + e]     = __float2half_rn(x0 - __half2float(hi0));
                        g_A2h_lo[b * 1024 + e + 1] = __float2half_rn(x1 - __half2float(hi1));
                    }
                    __syncwarp();
                    if (s + 4 < 16) {
                        int en = ebase + wid * 2 + (s + 4) * 16;
                        const __half* src = fhb + (size_t)en * Pz;
                        __half* dst = wpipe + (s & 3) * 1152;
                        #pragma unroll
                        for (int q = 0; q < 5; q++) {
                            int cc = lane + q * 32;
                            if (cc < 144) {
                                int r = cc / 72, off = (cc % 72) * 8;
                                cp16(dst + r * 576 + off, src + (size_t)r * Pz + off);
                            }
                        }
                        CP_COMMIT();
                    }
                }
            }
        }
        gridsync();

        // ------------- Phase D: 8 j-cols/block, cp.async double-buffered A ---
        {
            __half* Bh = reinterpret_cast<__half*>(dyns);      // [8][1032]
            __half* Bl = Bh + 8256;
            __half* Abase = reinterpret_cast<__half*>(dyns + 33024);
            // stage s: Ah = Abase + s*10240, Al = Ah + 5120  (halves, row stride 40)
            int j0g = bx * 8;
            #pragma unroll
            for (int q = 0; q < 4; q++) {
                int cc = tid + q * 256;
                int j = cc >> 7, off = (cc & 127) * 8;
                *reinterpret_cast<uint4*>(Bh + j * 1032 + off) =
                    *reinterpret_cast<const uint4*>(g_W2h_hi + (size_t)(j0g + j) * 1024 + off);
                *reinterpret_cast<uint4*>(Bl + j * 1032 + off) =
                    *reinterpret_cast<const uint4*>(g_W2h_lo + (size_t)(j0g + j) * 1024 + off);
            }
            #pragma unroll
            for (int q = 0; q < 2; q++) {              // prime tile 0
                int cc = tid + q * 256;
                int ar = cc >> 2, ao = (cc & 3) * 8;
                cp16(Abase + ar * 40 + ao, g_A2h_hi + ar * 1024 + ao);
                cp16(Abase + 5120 + ar * 40 + ao, g_A2h_lo + ar * 1024 + ao);
            }
            CP_COMMIT();
            int m0 = wid * 16;
            float c0 = 0.f, c1 = 0.f, c2 = 0.f, c3 = 0.f;
            for (int tt = 0; tt < 32; tt++) {
                if (tt + 1 < 32) {
                    __half* AhN = Abase + ((tt + 1) & 1) * 10240;
                    int k0n = (tt + 1) * 32;
                    #pragma unroll
                    for (int q = 0; q < 2; q++) {
                        int cc = tid + q * 256;
                        int ar = cc >> 2, ao = (cc & 3) * 8;
                        cp16(AhN + ar * 40 + ao, g_A2h_hi + ar * 1024 + k0n + ao);
                        cp16(AhN + 5120 + ar * 40 + ao, g_A2h_lo + ar * 1024 + k0n + ao);
                    }
                    CP_COMMIT();
                    CP_WAIT(1);
                } else {
                    CP_WAIT(0);
                }
                __syncthreads();
                const __half* Ah = Abase + (tt & 1) * 10240;
                const __half* Al = Ah + 5120;
                int k0 = tt * 32;
                #pragma unroll
                for (int kin = 0; kin < 2; kin++) {
                    int kk = kin * 16;
                    unsigned a0, a1, a2, a3, l0, l1, l2, l3, b0, b1, q0, q1;
                    ldsm4(a0, a1, a2, a3,
                          Ah + (m0 + (lane & 15)) * 40 + kk + (lane >> 4) * 8);
                    ldsm4(l0, l1, l2, l3,
                          Al + (m0 + (lane & 15)) * 40 + kk + (lane >> 4) * 8);
                    ldsm2(b0, b1,
                          Bh + (lane & 7) * 1032 + k0 + kk + ((lane >> 3) & 1) * 8);
                    ldsm2(q0, q1,
                          Bl + (lane & 7) * 1032 + k0 + kk + ((lane >> 3) & 1) * 8);
                    mma16816(c0, c1, c2, c3, a0, a1, a2, a3, b0, b1);
                    mma16816(c0, c1, c2, c3, a0, a1, a2, a3, q0, q1);
                    mma16816(c0, c1, c2, c3, l0, l1, l2, l3, b0, b1);
                }
                __syncthreads();
            }
            int bb = m0 + (lane >> 2);
            int jj = j0g + (lane & 3) * 2;
            float2 v0 = {c0, c1};
            float2 v1 = {c2, c3};
            *reinterpret_cast<float2*>(&g_gate[bb * 2048 + jj]) = v0;
            *reinterpret_cast<float2*>(&g_gate[(bb + 8) * 2048 + jj]) = v1;
        }
        gridsync();

        // ------------- Phase E: cell (redundant in pair) + split pred gemm ---
        {
            const int b = bb_;
            float* h2s = smf;            // 512
            const float* cprev = g_c[cur];
            float* cnext = g_c[cur ^ 1];
            float* hnext = g_h[cur ^ 1];
            int cap = captions[b * Tz + t];
            const float* ew = g_embW + (size_t)cap * 2048;
            const float* gp = g_gate + b * 2048;
            for (int d = tid; d < 512; d += NTHR) {
                float gi = bih[d]        + bhh[d]        + ew[d]        + gp[d];
                float gf = bih[512 + d]  + bhh[512 + d]  + ew[512 + d]  + gp[512 + d];
                float gg = bih[1024 + d] + bhh[1024 + d] + ew[1024 + d] + gp[1024 + d];
                float go = bih[1536 + d] + bhh[1536 + d] + ew[1536 + d] + gp[1536 + d];
                float c2 = fast_sigmoid(gf) * cprev[b * 512 + d]
                         + fast_sigmoid(gi) * fast_tanh(gg);
                float h2 = fast_sigmoid(go) * fast_tanh(c2);
                if (half == 0) {                       // one writer per value
                    cnext[b * 512 + d] = c2;
                    hnext[b * 512 + d] = h2;
                    __half hi = __float2half_rn(h2);
                    g_A2h_hi[b * 1024 + 512 + d] = hi;
                    g_A2h_lo[b * 1024 + 512 + d] = __float2half_rn(h2 - __half2float(hi));
                }
                h2s[d] = h2;
            }
            __syncthreads();
            float msk = ((lengths[b] - 1) > t) ? 1.0f : 0.0f;
            int v = -1;
            if (half == 0) { if (tid < 138) v = tid; }
            else           { if (tid < 137) v = 138 + tid; }
            if (v >= 0) {
                const float* row = g_fcwT + v * 512;
                float a0 = 0.f, a1 = 0.f, a2 = 0.f, a3 = 0.f;
                #pragma unroll 8
                for (int d = 0; d < 512; d += 4) {
                    float4 w = *reinterpret_cast<const float4*>(row + d);
                    float4 hh = *reinterpret_cast<const float4*>(h2s + d);
                    a0 = fmaf(hh.x, w.x, a0);
                    a1 = fmaf(hh.y, w.y, a1);
                    a2 = fmaf(hh.z, w.z, a2);
                    a3 = fmaf(hh.w, w.w, a3);
                }
                float acc = fcb[v] + ((a0 + a1) + (a2 + a3));
                preds_out[((size_t)b * TM1 + t) * Vz + v] = acc * msk;
            }
            __syncthreads();
        }
        gridsync();
    }
}

// ---------------- launch ------------------------------------------------------
extern "C" void kernel_launch(void* const* d_in, const int* in_sizes, int n_in,
                              void* d_out, int out_size) {
    const float* feats    = (const float*)d_in[0];
    const int*   captions = (const int*)d_in[1];
    const int*   lengths  = (const int*)d_in[2];
    const float* U_w  = (const float*)d_in[3];
    const float* U_b  = (const float*)d_in[4];
    const float* W_w  = (const float*)d_in[5];
    const float* W_b  = (const float*)d_in[6];
    const float* v_w  = (const float*)d_in[7];
    const float* v_b  = (const float*)d_in[8];
    const float* ihw  = (const float*)d_in[9];
    const float* ihb  = (const float*)d_in[10];
    const float* icw  = (const float*)d_in[11];
    const float* icb  = (const float*)d_in[12];
    const float* fbw  = (const float*)d_in[13];
    const float* fbb  = (const float*)d_in[14];
    const float* fcw  = (const float*)d_in[15];
    const float* fcb  = (const float*)d_in[16];
    const float* emb  = (const float*)d_in[17];
    const float* wih  = (const float*)d_in[18];
    const float* whh  = (const float*)d_in[19];
    const float* bih  = (const float*)d_in[20];
    const float* bhh  = (const float*)d_in[21];

    float* out    = (float*)d_out;
    float* preds  = out;
    float* alphas = out + (size_t)Bz * TM1 * Vz;
    float* dec    = alphas + (size_t)Bz * TM1 * Pz;

    cudaFuncSetAttribute(decode_kernel,
                         cudaFuncAttributeMaxDynamicSharedMemorySize, DSMEM);

    prep_misc_kernel<<<17210, 256>>>(feats, fcw, emb, wih, whh, lengths, dec);
    prep2_kernel<<<18448, 256>>>(feats, ihw, icw, ihb, icb);
    ws_gemm_kernel<<<dim3(9, 8, Bz), 256>>>(feats, W_w, W_b);
    decode_kernel<<<GRID, NTHR, DSMEM>>>(U_w, U_b, v_w, v_b, fbw, fbb,
                                         captions, lengths,
                                         bih, bhh, fcb,
                                         preds, alphas);
    (void)in_sizes; (void)n_in; (void)out_size;
}

// round 16
// speedup vs baseline: 1.1208x; 1.1208x over previous
#include <cuda_runtime.h>
#include <cuda_fp16.h>
#include <cstdint>
#include <cstddef>

#define Bz 128
#define Ez 512
#define Dz 512
#define Vz 275
#define Pz 576
#define Tz 300
#define TM1 299
#define EP (Ez*Pz)
#define GRID 128
#define NTHR 512
#define DSMEM 159744   // 12288 scratch + 147456 ctx pipe (score pipe / A 49KB fit)

// ---------------- scratch (device globals; no allocs allowed) ----------------
__device__ __align__(16) __half g_Ws[(size_t)Bz*Pz*Dz];     // fp16 flat@W_w + W_b
__device__ __align__(16) __half g_featsh[(size_t)Bz*EP];    // fp16 feats
__device__ __align__(16) float g_fcwT[Vz*Dz];               // fc weights [V][D]
__device__ __align__(16) float g_embW[Vz*2048];             // emb @ wih[:, :512]^T
__device__ __align__(16) float g_mean[Bz*Ez];
__device__ __align__(16) float g_h[2][Bz*Dz];
__device__ __align__(16) float g_c[2][Bz*Dz];
__device__ __align__(16) float g_p1[8][Bz*1024];            // (hU|gate) split-K partials
__device__ __align__(16) float g_gate[Bz*2048];             // LSTM gates (mma output)
__device__ __align__(16) __half g_A2h_hi[Bz*1024];          // [ctx | h] fp16 hi
__device__ __align__(16) __half g_A2h_lo[Bz*1024];          // residual lo
__device__ __align__(16) __half g_W2h_hi[(size_t)2048*1024];// [wih(ctx part) | whh] hi
__device__ __align__(16) __half g_W2h_lo[(size_t)2048*1024];// residual lo

// ---------------- software grid barrier --------------------------------------
__device__ unsigned g_bar_count;
__device__ volatile unsigned g_bar_gen;

__device__ __forceinline__ void gridsync() {
    __syncthreads();
    if (threadIdx.x == 0) {
        __threadfence();
        unsigned gen = g_bar_gen;
        if (atomicAdd(&g_bar_count, 1u) == GRID - 1) {
            g_bar_count = 0;
            __threadfence();
            g_bar_gen = gen + 1;
        } else {
            while (g_bar_gen == gen) {}
        }
        __threadfence();
    }
    __syncthreads();
}

// ---------------- async copy / mma helpers -----------------------------------
__device__ __forceinline__ void cp16(void* dst_smem, const void* src) {
    unsigned d = (unsigned)__cvta_generic_to_shared(dst_smem);
    asm volatile("cp.async.cg.shared.global [%0], [%1], 16;"
                 :: "r"(d), "l"(src) : "memory");
}
#define CP_COMMIT() asm volatile("cp.async.commit_group;" ::: "memory")
#define CP_WAIT(n)  asm volatile("cp.async.wait_group %0;" :: "n"(n) : "memory")
__device__ __forceinline__ void cp_wait_dyn(int n) {
    if (n >= 3)      { CP_WAIT(3); }
    else if (n == 2) { CP_WAIT(2); }
    else if (n == 1) { CP_WAIT(1); }
    else             { CP_WAIT(0); }
}

__device__ __forceinline__ void ldsm4(unsigned& r0, unsigned& r1, unsigned& r2,
                                      unsigned& r3, const void* p) {
    unsigned a = (unsigned)__cvta_generic_to_shared(p);
    asm volatile("ldmatrix.sync.aligned.m8n8.x4.shared.b16 {%0,%1,%2,%3}, [%4];"
                 : "=r"(r0), "=r"(r1), "=r"(r2), "=r"(r3) : "r"(a));
}
__device__ __forceinline__ void ldsm2(unsigned& r0, unsigned& r1, const void* p) {
    unsigned a = (unsigned)__cvta_generic_to_shared(p);
    asm volatile("ldmatrix.sync.aligned.m8n8.x2.shared.b16 {%0,%1}, [%2];"
                 : "=r"(r0), "=r"(r1) : "r"(a));
}
__device__ __forceinline__ void mma16816(float& c0, float& c1, float& c2, float& c3,
                                         unsigned a0, unsigned a1, unsigned a2,
                                         unsigned a3, unsigned b0, unsigned b1) {
    asm volatile("mma.sync.aligned.m16n8k16.row.col.f32.f16.f16.f32 "
                 "{%0,%1,%2,%3}, {%4,%5,%6,%7}, {%8,%9}, {%0,%1,%2,%3};"
                 : "+f"(c0), "+f"(c1), "+f"(c2), "+f"(c3)
                 : "r"(a0), "r"(a1), "r"(a2), "r"(a3), "r"(b0), "r"(b1));
}

// ---------------- activation helpers -----------------------------------------
__device__ __forceinline__ __half2 tanh2(__half2 x) {
    unsigned xi = *reinterpret_cast<unsigned*>(&x);
    unsigned yi;
    asm("tanh.approx.f16x2 %0, %1;" : "=r"(yi) : "r"(xi));
    return *reinterpret_cast<__half2*>(&yi);
}
__device__ __forceinline__ float fast_tanh(float x) {
    float t = fminf(fmaxf(x * 2.885390081777927f, -252.0f), 252.0f);
    float z; asm("ex2.approx.f32 %0, %1;" : "=f"(z) : "f"(t));
    float den = z + 1.0f;
    float r; asm("rcp.approx.f32 %0, %1;" : "=f"(r) : "f"(den));
    return (z - 1.0f) * r;
}
__device__ __forceinline__ float fast_sigmoid(float x) {
    float t = fminf(fmaxf(x * -1.4426950408889634f, -252.0f), 252.0f);
    float z; asm("ex2.approx.f32 %0, %1;" : "=f"(z) : "f"(t));
    float den = z + 1.0f;
    float r; asm("rcp.approx.f32 %0, %1;" : "=f"(r) : "f"(den));
    return r;
}

// ======= launch 1: mean + fcwT + embW + W2h(hi/lo) + dec_len =================
__global__ void prep_misc_kernel(const float* __restrict__ feats,
                                 const float* __restrict__ fcw,
                                 const float* __restrict__ emb,
                                 const float* __restrict__ wih,
                                 const float* __restrict__ whh,
                                 const int* __restrict__ lengths,
                                 float* __restrict__ dec) {
    __shared__ float er[512];
    int bx = blockIdx.x, tid = threadIdx.x;
    if (bx < 8192) {                                  // mean over P
        int warp = tid >> 5, lane = tid & 31;
        int idx = bx * 8 + warp;
        int b = idx >> 9, e = idx & 511;
        const float* src = feats + (size_t)b * EP + (size_t)e * Pz;
        float acc = 0.f;
        #pragma unroll
        for (int k = 0; k < 18; k++) acc += src[lane + k * 32];
        #pragma unroll
        for (int o = 16; o; o >>= 1) acc += __shfl_down_sync(0xffffffffu, acc, o);
        if (lane == 0) g_mean[idx] = acc * (1.0f / 576.0f);
    } else if (bx < 8742) {                           // fcw transpose
        int idx = (bx - 8192) * 256 + tid;
        int v = idx >> 9, d = idx & 511;
        g_fcwT[v * 512 + d] = fcw[d * Vz + v];
    } else if (bx < 9017) {                           // embW: one token per block
        int v = bx - 8742;
        for (int i = tid; i < 512; i += 256) er[i] = emb[v * 512 + i];
        __syncthreads();
        for (int j = tid; j < 2048; j += 256) {
            const float* wr = wih + (size_t)j * 1024;
            float a0 = 0.f, a1 = 0.f, a2 = 0.f, a3 = 0.f;
            #pragma unroll 8
            for (int k = 0; k < 512; k += 4) {
                float4 w = *reinterpret_cast<const float4*>(wr + k);
                float4 e4 = *reinterpret_cast<const float4*>(&er[k]);
                a0 = fmaf(w.x, e4.x, a0);
                a1 = fmaf(w.y, e4.y, a1);
                a2 = fmaf(w.z, e4.z, a2);
                a3 = fmaf(w.w, e4.w, a3);
            }
            g_embW[v * 2048 + j] = (a0 + a1) + (a2 + a3);
        }
    } else if (bx < 17209) {                          // W2h hi/lo
        int idx = (bx - 9017) * 256 + tid;            // < 2048*1024
        int j = idx >> 10, k = idx & 1023;
        float w = (k < 512) ? wih[(size_t)j * 1024 + 512 + k]
                            : whh[(size_t)j * 512 + (k - 512)];
        __half hi = __float2half_rn(w);
        g_W2h_hi[idx] = hi;
        g_W2h_lo[idx] = __float2half_rn(w - __half2float(hi));
    } else {                                          // dec_len
        if (tid < Bz) dec[tid] = (float)(lengths[tid] - 1);
    }
}

// ======= launch 2: f2h + init h0/c0 gemm (+ h0 fp16 hi/lo) ===================
__global__ void prep2_kernel(const float* __restrict__ feats,
                             const float* __restrict__ W1,
                             const float* __restrict__ W2,
                             const float* __restrict__ b1,
                             const float* __restrict__ b2) {
    int bx = blockIdx.x, tid = threadIdx.x;
    if (bx < 18432) {
        size_t i = ((size_t)bx * 256 + tid) * 8;
        float4 v0 = *reinterpret_cast<const float4*>(feats + i);
        float4 v1 = *reinterpret_cast<const float4*>(feats + i + 4);
        __half2 h0 = __floats2half2_rn(v0.x, v0.y);
        __half2 h1 = __floats2half2_rn(v0.z, v0.w);
        __half2 h2 = __floats2half2_rn(v1.x, v1.y);
        __half2 h3 = __floats2half2_rn(v1.z, v1.w);
        uint4 o;
        o.x = *reinterpret_cast<unsigned*>(&h0);
        o.y = *reinterpret_cast<unsigned*>(&h1);
        o.z = *reinterpret_cast<unsigned*>(&h2);
        o.w = *reinterpret_cast<unsigned*>(&h3);
        *reinterpret_cast<uint4*>(g_featsh + i) = o;
        return;
    }
    int jt = bx - 18432;
    const float* W = (jt < 8) ? W1 : W2;
    const float* bias = (jt < 8) ? b1 : b2;
    int wj0 = ((jt < 8) ? jt : jt - 8) * 64;
    __shared__ float As[8][128];
    __shared__ float Bs[8][64];
    int tx = tid & 15, ty = tid >> 4;
    float acc[8][4] = {};
    for (int kk = 0; kk < 512; kk += 8) {
        {
            int b = tid >> 1, r4 = (tid & 1) * 4;
            float4 v = *reinterpret_cast<const float4*>(&g_mean[b * 512 + kk + r4]);
            As[r4 + 0][b] = v.x; As[r4 + 1][b] = v.y; As[r4 + 2][b] = v.z; As[r4 + 3][b] = v.w;
        }
        if (tid < 128) {
            int j4 = (tid & 15) * 4, r = tid >> 4;
            float4 v = *reinterpret_cast<const float4*>(&W[(kk + r) * 512 + wj0 + j4]);
            Bs[r][j4 + 0] = v.x; Bs[r][j4 + 1] = v.y; Bs[r][j4 + 2] = v.z; Bs[r][j4 + 3] = v.w;
        }
        __syncthreads();
        #pragma unroll
        for (int r = 0; r < 8; r++) {
            float4 w4 = *reinterpret_cast<const float4*>(&Bs[r][tx * 4]);
            float4 a0 = *reinterpret_cast<const float4*>(&As[r][ty * 8]);
            float4 a1 = *reinterpret_cast<const float4*>(&As[r][ty * 8 + 4]);
            float a[8] = {a0.x, a0.y, a0.z, a0.w, a1.x, a1.y, a1.z, a1.w};
            float w[4] = {w4.x, w4.y, w4.z, w4.w};
            #pragma unroll
            for (int i = 0; i < 8; i++)
                #pragma unroll
                for (int jj = 0; jj < 4; jj++)
                    acc[i][jj] = fmaf(a[i], w[jj], acc[i][jj]);
        }
        __syncthreads();
    }
    float* dst = (jt < 8) ? g_h[0] : g_c[0];
    int j = wj0 + tx * 4;
    float4 bb = *reinterpret_cast<const float4*>(&bias[j]);
    #pragma unroll
    for (int i = 0; i < 8; i++) {
        int b = ty * 8 + i;
        float4 v = {acc[i][0] + bb.x, acc[i][1] + bb.y, acc[i][2] + bb.z, acc[i][3] + bb.w};
        *reinterpret_cast<float4*>(&dst[b * 512 + j]) = v;
        if (jt < 8) {
            #pragma unroll
            for (int q = 0; q < 4; q++) {
                float x = (&v.x)[q];
                __half hi = __float2half_rn(x);
                g_A2h_hi[b * 1024 + 512 + j + q] = hi;
                g_A2h_lo[b * 1024 + 512 + j + q] = __float2half_rn(x - __half2float(hi));
            }
        }
    }
}

// ======= launch 3: Ws precompute (fp16) ======================================
__global__ void ws_gemm_kernel(const float* __restrict__ feats,
                               const float* __restrict__ Ww,
                               const float* __restrict__ Wb) {
    int b = blockIdx.z;
    int p0 = blockIdx.x * 64;
    int d0 = blockIdx.y * 64;
    __shared__ float As[8][64];
    __shared__ float Bs[8][64];
    int tid = threadIdx.x, tx = tid & 15, ty = tid >> 4;
    float acc[4][4] = {};
    const float* fb = feats + (size_t)b * EP;
    for (int kk = 0; kk < 512; kk += 8) {
        if (tid < 128) {
            int p4 = (tid & 15) * 4, r = tid >> 4;
            float4 v = *reinterpret_cast<const float4*>(&fb[(size_t)(kk + r) * Pz + p0 + p4]);
            As[r][p4 + 0] = v.x; As[r][p4 + 1] = v.y; As[r][p4 + 2] = v.z; As[r][p4 + 3] = v.w;
        } else {
            int t2 = tid - 128;
            int d4 = (t2 & 15) * 4, r = t2 >> 4;
            float4 v = *reinterpret_cast<const float4*>(&Ww[(kk + r) * 512 + d0 + d4]);
            Bs[r][d4 + 0] = v.x; Bs[r][d4 + 1] = v.y; Bs[r][d4 + 2] = v.z; Bs[r][d4 + 3] = v.w;
        }
        __syncthreads();
        #pragma unroll
        for (int r = 0; r < 8; r++) {
            float4 a4 = *reinterpret_cast<const float4*>(&As[r][ty * 4]);
            float4 w4 = *reinterpret_cast<const float4*>(&Bs[r][tx * 4]);
            float a[4] = {a4.x, a4.y, a4.z, a4.w};
            float w[4] = {w4.x, w4.y, w4.z, w4.w};
            #pragma unroll
            for (int i = 0; i < 4; i++)
                #pragma unroll
                for (int jj = 0; jj < 4; jj++)
                    acc[i][jj] = fmaf(a[i], w[jj], acc[i][jj]);
        }
        __syncthreads();
    }
    float4 wb4 = *reinterpret_cast<const float4*>(&Wb[d0 + tx * 4]);
    #pragma unroll
    for (int i = 0; i < 4; i++) {
        size_t row = (size_t)(b * Pz + p0 + ty * 4 + i);
        __half2 h01 = __floats2half2_rn(acc[i][0] + wb4.x, acc[i][1] + wb4.y);
        __half2 h23 = __floats2half2_rn(acc[i][2] + wb4.z, acc[i][3] + wb4.w);
        uint2 u;
        u.x = *reinterpret_cast<unsigned*>(&h01);
        u.y = *reinterpret_cast<unsigned*>(&h23);
        *reinterpret_cast<uint2*>(&g_Ws[row * 512 + d0 + tx * 4]) = u;
    }
}

// ============================================================================
//  launch 4 (PROFILED): persistent decode, 299 steps, 4 phases/step
//  R14 baseline; Phase A single k-slab (one __syncthreads)
// ============================================================================
__global__ void __launch_bounds__(NTHR, 1) decode_kernel(
    const float* __restrict__ Uw,  const float* __restrict__ Ub,
    const float* __restrict__ vw,  const float* __restrict__ vb,
    const float* __restrict__ fbw, const float* __restrict__ fbb,
    const int*   __restrict__ captions,
    const int*   __restrict__ lengths,
    const float* __restrict__ bih, const float* __restrict__ bhh,
    const float* __restrict__ fcb,
    float* __restrict__ preds_out, float* __restrict__ alphas_out)
{
    extern __shared__ __align__(16) char dyns[];
    float* smf = reinterpret_cast<float*>(dyns);
    const int bx = blockIdx.x, tid = threadIdx.x;
    const int wid = tid >> 5, lane = tid & 31;

    for (int t = 0; t < TM1; t++) {
        const int cur = t & 1;
        const float* h = g_h[cur];

        // ------------- Phase A: (hU | gate-raw) partials, single 64-K slab ---
        {
            int jt = bx & 15, kc = bx >> 4;
            const float* W = (jt < 8) ? Uw : fbw;
            int wj0 = ((jt < 8) ? jt : jt - 8) * 64;
            int k0 = kc * 64;
            float* As = smf;             // [64][128] = 8192 floats
            float* Bs = smf + 8192;      // [64][64]  = 4096 floats
            {   // load A slab: all 512 threads, 16 floats each
                int b = tid >> 2, q = (tid & 3) * 16;
                #pragma unroll
                for (int u = 0; u < 4; u++) {
                    float4 v = *reinterpret_cast<const float4*>(&h[b * 512 + k0 + q + u * 4]);
                    As[(q + u * 4 + 0) * 128 + b] = v.x;
                    As[(q + u * 4 + 1) * 128 + b] = v.y;
                    As[(q + u * 4 + 2) * 128 + b] = v.z;
                    As[(q + u * 4 + 3) * 128 + b] = v.w;
                }
            }
            {   // load W slab: 64 rows x 64 j, 8 floats/thread
                int r = tid >> 3, j8 = (tid & 7) * 8;
                float4 v0 = *reinterpret_cast<const float4*>(&W[(k0 + r) * 512 + wj0 + j8]);
                float4 v1 = *reinterpret_cast<const float4*>(&W[(k0 + r) * 512 + wj0 + j8 + 4]);
                *reinterpret_cast<float4*>(&Bs[r * 64 + j8]) = v0;
                *reinterpret_cast<float4*>(&Bs[r * 64 + j8 + 4]) = v1;
            }
            __syncthreads();
            int tx = tid & 15, ty = tid >> 4;        // tx: 16 j-quads, ty: 32 b-quads
            float acc[4][4] = {};
            #pragma unroll 8
            for (int r = 0; r < 64; r++) {
                float4 w4 = *reinterpret_cast<const float4*>(&Bs[r * 64 + tx * 4]);
                float4 a4 = *reinterpret_cast<const float4*>(&As[r * 128 + ty * 4]);
                float a[4] = {a4.x, a4.y, a4.z, a4.w};
                float w[4] = {w4.x, w4.y, w4.z, w4.w};
                #pragma unroll
                for (int i = 0; i < 4; i++)
                    #pragma unroll
                    for (int jj = 0; jj < 4; jj++)
                        acc[i][jj] = fmaf(a[i], w[jj], acc[i][jj]);
            }
            float* pOut = g_p1[kc];
            int jg = jt * 64 + tx * 4;
            #pragma unroll
            for (int i = 0; i < 4; i++) {
                int b = ty * 4 + i;
                float4 v = {acc[i][0], acc[i][1], acc[i][2], acc[i][3]};
                *reinterpret_cast<float4*>(&pOut[b * 1024 + jg]) = v;
            }
            __syncthreads();
        }
        gridsync();

        // ------------- Phase BC: attention + softmax + ctx (block = b) -------
        {
            const int b = bx;
            float* hU = smf;             // [0, 512)
            float* gs = smf + 512;       // [512, 1024)
            float* es = smf + 1024;      // [1024, 1600)
            float* red = smf + 1600;     // [1600, 2112)
            __half2* hU2s = reinterpret_cast<__half2*>(smf + 2112);  // fl [2112,2368)
            __half2* vs2s = reinterpret_cast<__half2*>(smf + 2368);  // fl [2368,2624)
            __half2* es2s = reinterpret_cast<__half2*>(smf + 2624);  // fl [2624,2912)
            __half* pipe = reinterpret_cast<__half*>(dyns + 12288);
            {
                int d = tid;
                float s = Ub[d], g = fbb[d];
                #pragma unroll
                for (int kc = 0; kc < 8; kc++) {
                    s += g_p1[kc][b * 1024 + d];
                    g += g_p1[kc][b * 1024 + 512 + d];
                }
                hU[d] = s; gs[d] = fast_sigmoid(g);
            }
            __syncthreads();
            if (tid < 256) {
                hU2s[tid] = __floats2half2_rn(hU[2 * tid], hU[2 * tid + 1]);
                vs2s[tid] = __floats2half2_rn(vw[2 * tid], vw[2 * tid + 1]);
            }
            __syncthreads();
            float vb0 = vb[0];
            // ================= score: 18 per-warp stages (2 rows each) =======
            {
                const __half* wsb = g_Ws + (size_t)b * (Pz * 512);
                __half* wpipe = pipe + wid * 4096;   // 4 stages x 1024 halves
                #pragma unroll
                for (int s = 0; s < 4; s++) {
                    int p0 = wid * 2 + s * 32;
                    const __half* src = wsb + (size_t)p0 * 512;
                    __half* dst = wpipe + (s & 3) * 1024;
                    #pragma unroll
                    for (int q = 0; q < 4; q++) {
                        int cc = lane * 4 + q;       // 0..127 uint4
                        int r = cc >> 6, off = (cc & 63) * 8;
                        cp16(dst + r * 512 + off, src + (size_t)r * 512 + off);
                    }
                    CP_COMMIT();
                }
                for (int s = 0; s < 18; s++) {
                    cp_wait_dyn(17 - s < 3 ? 17 - s : 3);
                    __syncwarp();
                    const __half2* r0 = reinterpret_cast<const __half2*>(wpipe + (s & 3) * 1024);
                    const __half2* r1 = r0 + 256;
                    float a0 = 0.f, a1 = 0.f;
                    #pragma unroll
                    for (int k = 0; k < 2; k++) {
                        int d2 = lane * 4 + k * 128;
                        uint4 u0 = *reinterpret_cast<const uint4*>(r0 + d2);
                        uint4 u1 = *reinterpret_cast<const uint4*>(r1 + d2);
                        uint4 hu = *reinterpret_cast<const uint4*>(hU2s + d2);
                        uint4 vv = *reinterpret_cast<const uint4*>(vs2s + d2);
                        __half2 acc0 = __float2half2_rn(0.f);
                        __half2 acc1 = acc0;
                        #pragma unroll
                        for (int j = 0; j < 4; j++) {
                            __half2 hj = *reinterpret_cast<__half2*>(&(&hu.x)[j]);
                            __half2 vj = *reinterpret_cast<__half2*>(&(&vv.x)[j]);
                            __half2 w0 = *reinterpret_cast<__half2*>(&(&u0.x)[j]);
                            __half2 w1 = *reinterpret_cast<__half2*>(&(&u1.x)[j]);
                            acc0 = __hfma2(vj, tanh2(__hadd2(w0, hj)), acc0);
                            acc1 = __hfma2(vj, tanh2(__hadd2(w1, hj)), acc1);
                        }
                        float2 f0 = __half22float2(acc0);
                        float2 f1 = __half22float2(acc1);
                        a0 += f0.x + f0.y;
                        a1 += f1.x + f1.y;
                    }
                    #pragma unroll
                    for (int o = 16; o; o >>= 1) {
                        a0 += __shfl_down_sync(0xffffffffu, a0, o);
                        a1 += __shfl_down_sync(0xffffffffu, a1, o);
                    }
                    int p = wid * 2 + s * 32;
                    if (lane == 0) { es[p] = a0 + vb0; es[p + 1] = a1 + vb0; }
                    __syncwarp();
                    if (s + 4 < 18) {
                        int pn = wid * 2 + (s + 4) * 32;
                        const __half* src = wsb + (size_t)pn * 512;
                        __half* dst = wpipe + (s & 3) * 1024;
                        #pragma unroll
                        for (int q = 0; q < 4; q++) {
                            int cc = lane * 4 + q;
                            int r = cc >> 6, off = (cc & 63) * 8;
                            cp16(dst + r * 512 + off, src + (size_t)r * 512 + off);
                        }
                        CP_COMMIT();
                    }
                }
            }
            __syncthreads();
            // ---- softmax over 576
            float lmax = -1e30f;
            for (int p = tid; p < Pz; p += NTHR) lmax = fmaxf(lmax, es[p]);
            red[tid] = lmax; __syncthreads();
            for (int o = 256; o; o >>= 1) {
                if (tid < o) red[tid] = fmaxf(red[tid], red[tid + o]);
                __syncthreads();
            }
            float mx = red[0]; __syncthreads();
            float ls = 0.f;
            for (int p = tid; p < Pz; p += NTHR) {
                float v = __expf(es[p] - mx);
                es[p] = v; ls += v;
            }
            red[tid] = ls; __syncthreads();
            for (int o = 256; o; o >>= 1) {
                if (tid < o) red[tid] += red[tid + o];
                __syncthreads();
            }
            float inv = 1.0f / red[0];
            float msk = ((lengths[b] - 1) > t) ? 1.0f : 0.0f;
            for (int p = tid; p < Pz; p += NTHR) {
                float a = es[p] * inv;
                es[p] = a;
                alphas_out[((size_t)b * TM1 + t) * Pz + p] = a * msk;
            }
            __syncthreads();
            if (tid < 288)
                es2s[tid] = __floats2half2_rn(es[2 * tid], es[2 * tid + 1]);
            __syncthreads();
            // ================= ctx: 16 per-warp stages (2 e-rows each) =======
            {
                const __half* fhb = g_featsh + (size_t)b * EP;
                __half* wpipe = pipe + wid * 4608;   // 4 stages x 1152 halves
                #pragma unroll
                for (int s = 0; s < 4; s++) {
                    int e0 = wid * 2 + s * 32;
                    const __half* src = fhb + (size_t)e0 * Pz;
                    __half* dst = wpipe + (s & 3) * 1152;
                    #pragma unroll
                    for (int q = 0; q < 5; q++) {
                        int cc = lane + q * 32;      // 0..143 uint4
                        if (cc < 144) {
                            int r = cc / 72, off = (cc % 72) * 8;
                            cp16(dst + r * 576 + off, src + (size_t)r * Pz + off);
                        }
                    }
                    CP_COMMIT();
                }
                for (int s = 0; s < 16; s++) {
                    cp_wait_dyn(15 - s < 3 ? 15 - s : 3);
                    __syncwarp();
                    const __half2* r0 = reinterpret_cast<const __half2*>(wpipe + (s & 3) * 1152);
                    const __half2* r1 = r0 + 288;
                    float a0 = 0.f, a1 = 0.f;
                    #pragma unroll
                    for (int k = 0; k < 2; k++) {
                        int d2 = lane * 4 + k * 128;
                        uint4 u0 = *reinterpret_cast<const uint4*>(r0 + d2);
                        uint4 u1 = *reinterpret_cast<const uint4*>(r1 + d2);
                        uint4 ev = *reinterpret_cast<const uint4*>(es2s + d2);
                        __half2 acc0 = __float2half2_rn(0.f);
                        __half2 acc1 = acc0;
                        #pragma unroll
                        for (int j = 0; j < 4; j++) {
                            __half2 ej = *reinterpret_cast<__half2*>(&(&ev.x)[j]);
                            __half2 w0 = *reinterpret_cast<__half2*>(&(&u0.x)[j]);
                            __half2 w1 = *reinterpret_cast<__half2*>(&(&u1.x)[j]);
                            acc0 = __hfma2(w0, ej, acc0);
                            acc1 = __hfma2(w1, ej, acc1);
                        }
                        float2 f0 = __half22float2(acc0);
                        float2 f1 = __half22float2(acc1);
                        a0 += f0.x + f0.y;
                        a1 += f1.x + f1.y;
                    }
                    if (lane < 8) {                  // tail p = 512..575
                        int d2 = 256 + lane * 4;
                        uint4 u0 = *reinterpret_cast<const uint4*>(r0 + d2);
                        uint4 u1 = *reinterpret_cast<const uint4*>(r1 + d2);
                        uint4 ev = *reinterpret_cast<const uint4*>(es2s + d2);
                        __half2 acc0 = __float2half2_rn(0.f);
                        __half2 acc1 = acc0;
                        #pragma unroll
                        for (int j = 0; j < 4; j++) {
                            __half2 ej = *reinterpret_cast<__half2*>(&(&ev.x)[j]);
                            __half2 w0 = *reinterpret_cast<__half2*>(&(&u0.x)[j]);
                            __half2 w1 = *reinterpret_cast<__half2*>(&(&u1.x)[j]);
                            acc0 = __hfma2(w0, ej, acc0);
                            acc1 = __hfma2(w1, ej, acc1);
                        }
                        float2 f0 = __half22float2(acc0);
                        float2 f1 = __half22float2(acc1);
                        a0 += f0.x + f0.y;
                        a1 += f1.x + f1.y;
                    }
                    #pragma unroll
                    for (int o = 16; o; o >>= 1) {
                        a0 += __shfl_down_sync(0xffffffffu, a0, o);
                        a1 += __shfl_down_sync(0xffffffffu, a1, o);
                    }
                    int e = wid * 2 + s * 32;
                    if (lane == 0) {
                        float x0 = gs[e] * a0;
                        float x1 = gs[e + 1] * a1;
                        __half hi0 = __float2half_rn(x0);
                        __half hi1 = __float2half_rn(x1);
                        g_A2h_hi[b * 1024 + e]     = hi0;
                        g_A2h_hi[b * 1024 + e + 1] = hi1;
                        g_A2h_lo[b * 1024 + e]     = __float2half_rn(x0 - __half2float(hi0));
                        g_A2h_lo[b * 1024 + e + 1] = __float2half_rn(x1 - __half2float(hi1));
                    }
                    __syncwarp();
                    if (s + 4 < 16) {
                        int en = wid * 2 + (s + 4) * 32;
                        const __half* src = fhb + (size_t)en * Pz;
                        __half* dst = wpipe + (s & 3) * 1152;
                        #pragma unroll
                        for (int q = 0; q < 5; q++) {
                            int cc = lane + q * 32;
                            if (cc < 144) {
                                int r = cc / 72, off = (cc % 72) * 8;
                                cp16(dst + r * 576 + off, src + (size_t)r * Pz + off);
                            }
                        }
                        CP_COMMIT();
                    }
                }
            }
        }
        gridsync();

        // ------------- Phase D: gates = A2 @ W2^T via mma (fp16 hi/lo, 3-term)
        {
            __half* Bh = reinterpret_cast<__half*>(dyns);      // [16][1032]
            __half* Bl = Bh + 16512;
            __half* Ah = Bl + 16512;                           // [128][72]
            __half* Al = Ah + 9216;
            int j0g = bx * 16;
            #pragma unroll
            for (int q = 0; q < 4; q++) {
                int cc = tid + q * 512;
                int j = cc >> 7, off = (cc & 127) * 8;
                *reinterpret_cast<uint4*>(Bh + j * 1032 + off) =
                    *reinterpret_cast<const uint4*>(g_W2h_hi + (size_t)(j0g + j) * 1024 + off);
                *reinterpret_cast<uint4*>(Bl + j * 1032 + off) =
                    *reinterpret_cast<const uint4*>(g_W2h_lo + (size_t)(j0g + j) * 1024 + off);
            }
            int cc0 = tid * 2, cc1 = tid * 2 + 1;
            int ar0 = cc0 >> 3, ao0 = (cc0 & 7) * 8;
            int ar1 = cc1 >> 3, ao1 = (cc1 & 7) * 8;
            uint4 pa0 = *reinterpret_cast<const uint4*>(g_A2h_hi + ar0 * 1024 + ao0);
            uint4 pa1 = *reinterpret_cast<const uint4*>(g_A2h_hi + ar1 * 1024 + ao1);
            uint4 pl0 = *reinterpret_cast<const uint4*>(g_A2h_lo + ar0 * 1024 + ao0);
            uint4 pl1 = *reinterpret_cast<const uint4*>(g_A2h_lo + ar1 * 1024 + ao1);
            int m0 = (wid >> 1) * 16, n0 = (wid & 1) * 8;
            float c0 = 0.f, c1 = 0.f, c2 = 0.f, c3 = 0.f;
            for (int tt = 0; tt < 16; tt++) {
                *reinterpret_cast<uint4*>(Ah + ar0 * 72 + ao0) = pa0;
                *reinterpret_cast<uint4*>(Ah + ar1 * 72 + ao1) = pa1;
                *reinterpret_cast<uint4*>(Al + ar0 * 72 + ao0) = pl0;
                *reinterpret_cast<uint4*>(Al + ar1 * 72 + ao1) = pl1;
                __syncthreads();
                if (tt + 1 < 16) {
                    int k0n = (tt + 1) * 64;
                    pa0 = *reinterpret_cast<const uint4*>(g_A2h_hi + ar0 * 1024 + k0n + ao0);
                    pa1 = *reinterpret_cast<const uint4*>(g_A2h_hi + ar1 * 1024 + k0n + ao1);
                    pl0 = *reinterpret_cast<const uint4*>(g_A2h_lo + ar0 * 1024 + k0n + ao0);
                    pl1 = *reinterpret_cast<const uint4*>(g_A2h_lo + ar1 * 1024 + k0n + ao1);
                }
                int k0 = tt * 64;
                #pragma unroll
                for (int kin = 0; kin < 4; kin++) {
                    int kk = kin * 16;
                    unsigned a0, a1, a2, a3, l0, l1, l2, l3, b0, b1, q0, q1;
                    ldsm4(a0, a1, a2, a3,
                          Ah + (m0 + (lane & 15)) * 72 + kk + (lane >> 4) * 8);
                    ldsm4(l0, l1, l2, l3,
                          Al + (m0 + (lane & 15)) * 72 + kk + (lane >> 4) * 8);
                    ldsm2(b0, b1,
                          Bh + (n0 + (lane & 7)) * 1032 + k0 + kk + ((lane >> 3) & 1) * 8);
                    ldsm2(q0, q1,
                          Bl + (n0 + (lane & 7)) * 1032 + k0 + kk + ((lane >> 3) & 1) * 8);
                    mma16816(c0, c1, c2, c3, a0, a1, a2, a3, b0, b1);
                    mma16816(c0, c1, c2, c3, a0, a1, a2, a3, q0, q1);
                    mma16816(c0, c1, c2, c3, l0, l1, l2, l3, b0, b1);
                }
                __syncthreads();
            }
            int bb = m0 + (lane >> 2);
            int jj = j0g + n0 + (lane & 3) * 2;
            float2 v0 = {c0, c1};
            float2 v1 = {c2, c3};
            *reinterpret_cast<float2*>(&g_gate[bb * 2048 + jj]) = v0;
            *reinterpret_cast<float2*>(&g_gate[(bb + 8) * 2048 + jj]) = v1;
        }
        gridsync();

        // ------------- Phase E: gates + embW + LSTM cell + pred gemm
        {
            const int b = bx;
            float* h2s = smf;            // 512
            const float* cprev = g_c[cur];
            float* cnext = g_c[cur ^ 1];
            float* hnext = g_h[cur ^ 1];
            int cap = captions[b * Tz + t];
            const float* ew = g_embW + (size_t)cap * 2048;
            const float* gp = g_gate + b * 2048;
            {
                int d = tid;
                float gi = bih[d]        + bhh[d]        + ew[d]        + gp[d];
                float gf = bih[512 + d]  + bhh[512 + d]  + ew[512 + d]  + gp[512 + d];
                float gg = bih[1024 + d] + bhh[1024 + d] + ew[1024 + d] + gp[1024 + d];
                float go = bih[1536 + d] + bhh[1536 + d] + ew[1536 + d] + gp[1536 + d];
                float c2 = fast_sigmoid(gf) * cprev[b * 512 + d]
                         + fast_sigmoid(gi) * fast_tanh(gg);
                float h2 = fast_sigmoid(go) * fast_tanh(c2);
                cnext[b * 512 + d] = c2;
                hnext[b * 512 + d] = h2;
                __half hi = __float2half_rn(h2);
                g_A2h_hi[b * 1024 + 512 + d] = hi;
                g_A2h_lo[b * 1024 + 512 + d] = __float2half_rn(h2 - __half2float(hi));
                h2s[d] = h2;
            }
            __syncthreads();
            float msk = ((lengths[b] - 1) > t) ? 1.0f : 0.0f;
            if (tid < Vz) {
                int v = tid;
                const float* row = g_fcwT + v * 512;
                float a0 = 0.f, a1 = 0.f, a2 = 0.f, a3 = 0.f;
                #pragma unroll 8
                for (int d = 0; d < 512; d += 4) {
                    float4 w = *reinterpret_cast<const float4*>(row + d);
                    float4 hh = *reinterpret_cast<const float4*>(h2s + d);
                    a0 = fmaf(hh.x, w.x, a0);
                    a1 = fmaf(hh.y, w.y, a1);
                    a2 = fmaf(hh.z, w.z, a2);
                    a3 = fmaf(hh.w, w.w, a3);
                }
                float acc = fcb[v] + ((a0 + a1) + (a2 + a3));
                preds_out[((size_t)b * TM1 + t) * Vz + v] = acc * msk;
            }
            __syncthreads();
        }
        gridsync();
    }
}

// ---------------- launch ------------------------------------------------------
extern "C" void kernel_launch(void* const* d_in, const int* in_sizes, int n_in,
                              void* d_out, int out_size) {
    const float* feats    = (const float*)d_in[0];
    const int*   captions = (const int*)d_in[1];
    const int*   lengths  = (const int*)d_in[2];
    const float* U_w  = (const float*)d_in[3];
    const float* U_b  = (const float*)d_in[4];
    const float* W_w  = (const float*)d_in[5];
    const float* W_b  = (const float*)d_in[6];
    const float* v_w  = (const float*)d_in[7];
    const float* v_b  = (const float*)d_in[8];
    const float* ihw  = (const float*)d_in[9];
    const float* ihb  = (const float*)d_in[10];
    const float* icw  = (const float*)d_in[11];
    const float* icb  = (const float*)d_in[12];
    const float* fbw  = (const float*)d_in[13];
    const float* fbb  = (const float*)d_in[14];
    const float* fcw  = (const float*)d_in[15];
    const float* fcb  = (const float*)d_in[16];
    const float* emb  = (const float*)d_in[17];
    const float* wih  = (const float*)d_in[18];
    const float* whh  = (const float*)d_in[19];
    const float* bih  = (const float*)d_in[20];
    const float* bhh  = (const float*)d_in[21];

    float* out    = (float*)d_out;
    float* preds  = out;
    float* alphas = out + (size_t)Bz * TM1 * Vz;
    float* dec    = alphas + (size_t)Bz * TM1 * Pz;

    cudaFuncSetAttribute(decode_kernel,
                         cudaFuncAttributeMaxDynamicSharedMemorySize, DSMEM);

    prep_misc_kernel<<<17210, 256>>>(feats, fcw, emb, wih, whh, lengths, dec);
    prep2_kernel<<<18448, 256>>>(feats, ihw, icw, ihb, icb);
    ws_gemm_kernel<<<dim3(9, 8, Bz), 256>>>(feats, W_w, W_b);
    decode_kernel<<<GRID, NTHR, DSMEM>>>(U_w, U_b, v_w, v_b, fbw, fbb,
                                         captions, lengths,
                                         bih, bhh, fcb,
                                         preds, alphas);
    (void)in_sizes; (void)n_in; (void)out_size;
}

// round 17
// speedup vs baseline: 1.1334x; 1.0112x over previous
#include <cuda_runtime.h>
#include <cuda_fp16.h>
#include <cstdint>
#include <cstddef>

#define Bz 128
#define Ez 512
#define Dz 512
#define Vz 275
#define Pz 576
#define Tz 300
#define TM1 299
#define EP (Ez*Pz)
#define GRID 128
#define NTHR 512
#define DSMEM 159744   // 12288 scratch + 147456 ctx pipe; D uses 139776

// ---------------- scratch (device globals; no allocs allowed) ----------------
__device__ __align__(16) __half g_Ws[(size_t)Bz*Pz*Dz];     // fp16 flat@W_w + W_b
__device__ __align__(16) __half g_featsh[(size_t)Bz*EP];    // fp16 feats
__device__ __align__(16) float g_fcwT[Vz*Dz];               // fc weights [V][D]
__device__ __align__(16) float g_embW[Vz*2048];             // emb @ wih[:, :512]^T
__device__ __align__(16) float g_mean[Bz*Ez];
__device__ __align__(16) float g_h[2][Bz*Dz];
__device__ __align__(16) float g_c[2][Bz*Dz];
__device__ __align__(16) float g_p1[8][Bz*1024];            // (hU|gate) split-K partials
__device__ __align__(16) float g_gate[Bz*2048];             // LSTM gates (mma output)
__device__ __align__(16) __half g_A2h_hi[Bz*1024];          // [ctx | h] fp16 hi
__device__ __align__(16) __half g_A2h_lo[Bz*1024];          // residual lo
__device__ __align__(16) __half g_W2h_hi[(size_t)2048*1024];// [wih(ctx part) | whh] hi
__device__ __align__(16) __half g_W2h_lo[(size_t)2048*1024];// residual lo

// ---------------- software grid barrier --------------------------------------
__device__ unsigned g_bar_count;
__device__ volatile unsigned g_bar_gen;

__device__ __forceinline__ void gridsync() {
    __syncthreads();
    if (threadIdx.x == 0) {
        __threadfence();
        unsigned gen = g_bar_gen;
        if (atomicAdd(&g_bar_count, 1u) == GRID - 1) {
            g_bar_count = 0;
            __threadfence();
            g_bar_gen = gen + 1;
        } else {
            while (g_bar_gen == gen) {}
        }
        __threadfence();
    }
    __syncthreads();
}

// ---------------- async copy / mma helpers -----------------------------------
__device__ __forceinline__ void cp16(void* dst_smem, const void* src) {
    unsigned d = (unsigned)__cvta_generic_to_shared(dst_smem);
    asm volatile("cp.async.cg.shared.global [%0], [%1], 16;"
                 :: "r"(d), "l"(src) : "memory");
}
#define CP_COMMIT() asm volatile("cp.async.commit_group;" ::: "memory")
#define CP_WAIT(n)  asm volatile("cp.async.wait_group %0;" :: "n"(n) : "memory")
__device__ __forceinline__ void cp_wait_dyn(int n) {
    if (n >= 3)      { CP_WAIT(3); }
    else if (n == 2) { CP_WAIT(2); }
    else if (n == 1) { CP_WAIT(1); }
    else             { CP_WAIT(0); }
}

__device__ __forceinline__ void ldsm4(unsigned& r0, unsigned& r1, unsigned& r2,
                                      unsigned& r3, const void* p) {
    unsigned a = (unsigned)__cvta_generic_to_shared(p);
    asm volatile("ldmatrix.sync.aligned.m8n8.x4.shared.b16 {%0,%1,%2,%3}, [%4];"
                 : "=r"(r0), "=r"(r1), "=r"(r2), "=r"(r3) : "r"(a));
}
__device__ __forceinline__ void ldsm2(unsigned& r0, unsigned& r1, const void* p) {
    unsigned a = (unsigned)__cvta_generic_to_shared(p);
    asm volatile("ldmatrix.sync.aligned.m8n8.x2.shared.b16 {%0,%1}, [%2];"
                 : "=r"(r0), "=r"(r1) : "r"(a));
}
__device__ __forceinline__ void mma16816(float& c0, float& c1, float& c2, float& c3,
                                         unsigned a0, unsigned a1, unsigned a2,
                                         unsigned a3, unsigned b0, unsigned b1) {
    asm volatile("mma.sync.aligned.m16n8k16.row.col.f32.f16.f16.f32 "
                 "{%0,%1,%2,%3}, {%4,%5,%6,%7}, {%8,%9}, {%0,%1,%2,%3};"
                 : "+f"(c0), "+f"(c1), "+f"(c2), "+f"(c3)
                 : "r"(a0), "r"(a1), "r"(a2), "r"(a3), "r"(b0), "r"(b1));
}

// ---------------- activation helpers -----------------------------------------
__device__ __forceinline__ __half2 tanh2(__half2 x) {
    unsigned xi = *reinterpret_cast<unsigned*>(&x);
    unsigned yi;
    asm("tanh.approx.f16x2 %0, %1;" : "=r"(yi) : "r"(xi));
    return *reinterpret_cast<__half2*>(&yi);
}
__device__ __forceinline__ float fast_tanh(float x) {
    float t = fminf(fmaxf(x * 2.885390081777927f, -252.0f), 252.0f);
    float z; asm("ex2.approx.f32 %0, %1;" : "=f"(z) : "f"(t));
    float den = z + 1.0f;
    float r; asm("rcp.approx.f32 %0, %1;" : "=f"(r) : "f"(den));
    return (z - 1.0f) * r;
}
__device__ __forceinline__ float fast_sigmoid(float x) {
    float t = fminf(fmaxf(x * -1.4426950408889634f, -252.0f), 252.0f);
    float z; asm("ex2.approx.f32 %0, %1;" : "=f"(z) : "f"(t));
    float den = z + 1.0f;
    float r; asm("rcp.approx.f32 %0, %1;" : "=f"(r) : "f"(den));
    return r;
}

// ======= launch 1: mean + fcwT + embW + W2h(hi/lo) + dec_len =================
__global__ void prep_misc_kernel(const float* __restrict__ feats,
                                 const float* __restrict__ fcw,
                                 const float* __restrict__ emb,
                                 const float* __restrict__ wih,
                                 const float* __restrict__ whh,
                                 const int* __restrict__ lengths,
                                 float* __restrict__ dec) {
    __shared__ float er[512];
    int bx = blockIdx.x, tid = threadIdx.x;
    if (bx < 8192) {                                  // mean over P
        int warp = tid >> 5, lane = tid & 31;
        int idx = bx * 8 + warp;
        int b = idx >> 9, e = idx & 511;
        const float* src = feats + (size_t)b * EP + (size_t)e * Pz;
        float acc = 0.f;
        #pragma unroll
        for (int k = 0; k < 18; k++) acc += src[lane + k * 32];
        #pragma unroll
        for (int o = 16; o; o >>= 1) acc += __shfl_down_sync(0xffffffffu, acc, o);
        if (lane == 0) g_mean[idx] = acc * (1.0f / 576.0f);
    } else if (bx < 8742) {                           // fcw transpose
        int idx = (bx - 8192) * 256 + tid;
        int v = idx >> 9, d = idx & 511;
        g_fcwT[v * 512 + d] = fcw[d * Vz + v];
    } else if (bx < 9017) {                           // embW: one token per block
        int v = bx - 8742;
        for (int i = tid; i < 512; i += 256) er[i] = emb[v * 512 + i];
        __syncthreads();
        for (int j = tid; j < 2048; j += 256) {
            const float* wr = wih + (size_t)j * 1024;
            float a0 = 0.f, a1 = 0.f, a2 = 0.f, a3 = 0.f;
            #pragma unroll 8
            for (int k = 0; k < 512; k += 4) {
                float4 w = *reinterpret_cast<const float4*>(wr + k);
                float4 e4 = *reinterpret_cast<const float4*>(&er[k]);
                a0 = fmaf(w.x, e4.x, a0);
                a1 = fmaf(w.y, e4.y, a1);
                a2 = fmaf(w.z, e4.z, a2);
                a3 = fmaf(w.w, e4.w, a3);
            }
            g_embW[v * 2048 + j] = (a0 + a1) + (a2 + a3);
        }
    } else if (bx < 17209) {                          // W2h hi/lo
        int idx = (bx - 9017) * 256 + tid;            // < 2048*1024
        int j = idx >> 10, k = idx & 1023;
        float w = (k < 512) ? wih[(size_t)j * 1024 + 512 + k]
                            : whh[(size_t)j * 512 + (k - 512)];
        __half hi = __float2half_rn(w);
        g_W2h_hi[idx] = hi;
        g_W2h_lo[idx] = __float2half_rn(w - __half2float(hi));
    } else {                                          // dec_len
        if (tid < Bz) dec[tid] = (float)(lengths[tid] - 1);
    }
}

// ======= launch 2: f2h + init h0/c0 gemm (+ h0 fp16 hi/lo) ===================
__global__ void prep2_kernel(const float* __restrict__ feats,
                             const float* __restrict__ W1,
                             const float* __restrict__ W2,
                             const float* __restrict__ b1,
                             const float* __restrict__ b2) {
    int bx = blockIdx.x, tid = threadIdx.x;
    if (bx < 18432) {
        size_t i = ((size_t)bx * 256 + tid) * 8;
        float4 v0 = *reinterpret_cast<const float4*>(feats + i);
        float4 v1 = *reinterpret_cast<const float4*>(feats + i + 4);
        __half2 h0 = __floats2half2_rn(v0.x, v0.y);
        __half2 h1 = __floats2half2_rn(v0.z, v0.w);
        __half2 h2 = __floats2half2_rn(v1.x, v1.y);
        __half2 h3 = __floats2half2_rn(v1.z, v1.w);
        uint4 o;
        o.x = *reinterpret_cast<unsigned*>(&h0);
        o.y = *reinterpret_cast<unsigned*>(&h1);
        o.z = *reinterpret_cast<unsigned*>(&h2);
        o.w = *reinterpret_cast<unsigned*>(&h3);
        *reinterpret_cast<uint4*>(g_featsh + i) = o;
        return;
    }
    int jt = bx - 18432;
    const float* W = (jt < 8) ? W1 : W2;
    const float* bias = (jt < 8) ? b1 : b2;
    int wj0 = ((jt < 8) ? jt : jt - 8) * 64;
    __shared__ float As[8][128];
    __shared__ float Bs[8][64];
    int tx = tid & 15, ty = tid >> 4;
    float acc[8][4] = {};
    for (int kk = 0; kk < 512; kk += 8) {
        {
            int b = tid >> 1, r4 = (tid & 1) * 4;
            float4 v = *reinterpret_cast<const float4*>(&g_mean[b * 512 + kk + r4]);
            As[r4 + 0][b] = v.x; As[r4 + 1][b] = v.y; As[r4 + 2][b] = v.z; As[r4 + 3][b] = v.w;
        }
        if (tid < 128) {
            int j4 = (tid & 15) * 4, r = tid >> 4;
            float4 v = *reinterpret_cast<const float4*>(&W[(kk + r) * 512 + wj0 + j4]);
            Bs[r][j4 + 0] = v.x; Bs[r][j4 + 1] = v.y; Bs[r][j4 + 2] = v.z; Bs[r][j4 + 3] = v.w;
        }
        __syncthreads();
        #pragma unroll
        for (int r = 0; r < 8; r++) {
            float4 w4 = *reinterpret_cast<const float4*>(&Bs[r][tx * 4]);
            float4 a0 = *reinterpret_cast<const float4*>(&As[r][ty * 8]);
            float4 a1 = *reinterpret_cast<const float4*>(&As[r][ty * 8 + 4]);
            float a[8] = {a0.x, a0.y, a0.z, a0.w, a1.x, a1.y, a1.z, a1.w};
            float w[4] = {w4.x, w4.y, w4.z, w4.w};
            #pragma unroll
            for (int i = 0; i < 8; i++)
                #pragma unroll
                for (int jj = 0; jj < 4; jj++)
                    acc[i][jj] = fmaf(a[i], w[jj], acc[i][jj]);
        }
        __syncthreads();
    }
    float* dst = (jt < 8) ? g_h[0] : g_c[0];
    int j = wj0 + tx * 4;
    float4 bb = *reinterpret_cast<const float4*>(&bias[j]);
    #pragma unroll
    for (int i = 0; i < 8; i++) {
        int b = ty * 8 + i;
        float4 v = {acc[i][0] + bb.x, acc[i][1] + bb.y, acc[i][2] + bb.z, acc[i][3] + bb.w};
        *reinterpret_cast<float4*>(&dst[b * 512 + j]) = v;
        if (jt < 8) {
            #pragma unroll
            for (int q = 0; q < 4; q++) {
                float x = (&v.x)[q];
                __half hi = __float2half_rn(x);
                g_A2h_hi[b * 1024 + 512 + j + q] = hi;
                g_A2h_lo[b * 1024 + 512 + j + q] = __float2half_rn(x - __half2float(hi));
            }
        }
    }
}

// ======= launch 3: Ws precompute (fp16) ======================================
__global__ void ws_gemm_kernel(const float* __restrict__ feats,
                               const float* __restrict__ Ww,
                               const float* __restrict__ Wb) {
    int b = blockIdx.z;
    int p0 = blockIdx.x * 64;
    int d0 = blockIdx.y * 64;
    __shared__ float As[8][64];
    __shared__ float Bs[8][64];
    int tid = threadIdx.x, tx = tid & 15, ty = tid >> 4;
    float acc[4][4] = {};
    const float* fb = feats + (size_t)b * EP;
    for (int kk = 0; kk < 512; kk += 8) {
        if (tid < 128) {
            int p4 = (tid & 15) * 4, r = tid >> 4;
            float4 v = *reinterpret_cast<const float4*>(&fb[(size_t)(kk + r) * Pz + p0 + p4]);
            As[r][p4 + 0] = v.x; As[r][p4 + 1] = v.y; As[r][p4 + 2] = v.z; As[r][p4 + 3] = v.w;
        } else {
            int t2 = tid - 128;
            int d4 = (t2 & 15) * 4, r = t2 >> 4;
            float4 v = *reinterpret_cast<const float4*>(&Ww[(kk + r) * 512 + d0 + d4]);
            Bs[r][d4 + 0] = v.x; Bs[r][d4 + 1] = v.y; Bs[r][d4 + 2] = v.z; Bs[r][d4 + 3] = v.w;
        }
        __syncthreads();
        #pragma unroll
        for (int r = 0; r < 8; r++) {
            float4 a4 = *reinterpret_cast<const float4*>(&As[r][ty * 4]);
            float4 w4 = *reinterpret_cast<const float4*>(&Bs[r][tx * 4]);
            float a[4] = {a4.x, a4.y, a4.z, a4.w};
            float w[4] = {w4.x, w4.y, w4.z, w4.w};
            #pragma unroll
            for (int i = 0; i < 4; i++)
                #pragma unroll
                for (int jj = 0; jj < 4; jj++)
                    acc[i][jj] = fmaf(a[i], w[jj], acc[i][jj]);
        }
        __syncthreads();
    }
    float4 wb4 = *reinterpret_cast<const float4*>(&Wb[d0 + tx * 4]);
    #pragma unroll
    for (int i = 0; i < 4; i++) {
        size_t row = (size_t)(b * Pz + p0 + ty * 4 + i);
        __half2 h01 = __floats2half2_rn(acc[i][0] + wb4.x, acc[i][1] + wb4.y);
        __half2 h23 = __floats2half2_rn(acc[i][2] + wb4.z, acc[i][3] + wb4.w);
        uint2 u;
        u.x = *reinterpret_cast<unsigned*>(&h01);
        u.y = *reinterpret_cast<unsigned*>(&h23);
        *reinterpret_cast<uint2*>(&g_Ws[row * 512 + d0 + tx * 4]) = u;
    }
}

// ============================================================================
//  launch 4 (PROFILED): persistent decode, 299 steps, 4 phases/step
//  R16 + double-buffered Phase D (1 sync/tile) + shuffle softmax (4 syncs)
// ============================================================================
__global__ void __launch_bounds__(NTHR, 1) decode_kernel(
    const float* __restrict__ Uw,  const float* __restrict__ Ub,
    const float* __restrict__ vw,  const float* __restrict__ vb,
    const float* __restrict__ fbw, const float* __restrict__ fbb,
    const int*   __restrict__ captions,
    const int*   __restrict__ lengths,
    const float* __restrict__ bih, const float* __restrict__ bhh,
    const float* __restrict__ fcb,
    float* __restrict__ preds_out, float* __restrict__ alphas_out)
{
    extern __shared__ __align__(16) char dyns[];
    float* smf = reinterpret_cast<float*>(dyns);
    const int bx = blockIdx.x, tid = threadIdx.x;
    const int wid = tid >> 5, lane = tid & 31;

    for (int t = 0; t < TM1; t++) {
        const int cur = t & 1;
        const float* h = g_h[cur];

        // ------------- Phase A: (hU | gate-raw) partials, single 64-K slab ---
        {
            int jt = bx & 15, kc = bx >> 4;
            const float* W = (jt < 8) ? Uw : fbw;
            int wj0 = ((jt < 8) ? jt : jt - 8) * 64;
            int k0 = kc * 64;
            float* As = smf;             // [64][128]
            float* Bs = smf + 8192;      // [64][64]
            {
                int b = tid >> 2, q = (tid & 3) * 16;
                #pragma unroll
                for (int u = 0; u < 4; u++) {
                    float4 v = *reinterpret_cast<const float4*>(&h[b * 512 + k0 + q + u * 4]);
                    As[(q + u * 4 + 0) * 128 + b] = v.x;
                    As[(q + u * 4 + 1) * 128 + b] = v.y;
                    As[(q + u * 4 + 2) * 128 + b] = v.z;
                    As[(q + u * 4 + 3) * 128 + b] = v.w;
                }
            }
            {
                int r = tid >> 3, j8 = (tid & 7) * 8;
                float4 v0 = *reinterpret_cast<const float4*>(&W[(k0 + r) * 512 + wj0 + j8]);
                float4 v1 = *reinterpret_cast<const float4*>(&W[(k0 + r) * 512 + wj0 + j8 + 4]);
                *reinterpret_cast<float4*>(&Bs[r * 64 + j8]) = v0;
                *reinterpret_cast<float4*>(&Bs[r * 64 + j8 + 4]) = v1;
            }
            __syncthreads();
            int tx = tid & 15, ty = tid >> 4;
            float acc[4][4] = {};
            #pragma unroll 8
            for (int r = 0; r < 64; r++) {
                float4 w4 = *reinterpret_cast<const float4*>(&Bs[r * 64 + tx * 4]);
                float4 a4 = *reinterpret_cast<const float4*>(&As[r * 128 + ty * 4]);
                float a[4] = {a4.x, a4.y, a4.z, a4.w};
                float w[4] = {w4.x, w4.y, w4.z, w4.w};
                #pragma unroll
                for (int i = 0; i < 4; i++)
                    #pragma unroll
                    for (int jj = 0; jj < 4; jj++)
                        acc[i][jj] = fmaf(a[i], w[jj], acc[i][jj]);
            }
            float* pOut = g_p1[kc];
            int jg = jt * 64 + tx * 4;
            #pragma unroll
            for (int i = 0; i < 4; i++) {
                int b = ty * 4 + i;
                float4 v = {acc[i][0], acc[i][1], acc[i][2], acc[i][3]};
                *reinterpret_cast<float4*>(&pOut[b * 1024 + jg]) = v;
            }
            __syncthreads();
        }
        gridsync();

        // ------------- Phase BC: attention + softmax + ctx (block = b) -------
        {
            const int b = bx;
            float* hU = smf;             // [0, 512)
            float* gs = smf + 512;       // [512, 1024)
            float* es = smf + 1024;      // [1024, 1600)
            float* red = smf + 1600;     // [1600, 1632) -- 18 slots used
            __half2* hU2s = reinterpret_cast<__half2*>(smf + 2112);  // fl [2112,2368)
            __half2* vs2s = reinterpret_cast<__half2*>(smf + 2368);  // fl [2368,2624)
            __half2* es2s = reinterpret_cast<__half2*>(smf + 2624);  // fl [2624,2912)
            __half* pipe = reinterpret_cast<__half*>(dyns + 12288);
            {
                int d = tid;
                float s = Ub[d], g = fbb[d];
                #pragma unroll
                for (int kc = 0; kc < 8; kc++) {
                    s += g_p1[kc][b * 1024 + d];
                    g += g_p1[kc][b * 1024 + 512 + d];
                }
                hU[d] = s; gs[d] = fast_sigmoid(g);
            }
            __syncthreads();
            if (tid < 256) {
                hU2s[tid] = __floats2half2_rn(hU[2 * tid], hU[2 * tid + 1]);
                vs2s[tid] = __floats2half2_rn(vw[2 * tid], vw[2 * tid + 1]);
            }
            __syncthreads();
            float vb0 = vb[0];
            // ================= score: 18 per-warp stages (2 rows each) =======
            {
                const __half* wsb = g_Ws + (size_t)b * (Pz * 512);
                __half* wpipe = pipe + wid * 4096;   // 4 stages x 1024 halves
                #pragma unroll
                for (int s = 0; s < 4; s++) {
                    int p0 = wid * 2 + s * 32;
                    const __half* src = wsb + (size_t)p0 * 512;
                    __half* dst = wpipe + (s & 3) * 1024;
                    #pragma unroll
                    for (int q = 0; q < 4; q++) {
                        int cc = lane * 4 + q;       // 0..127 uint4
                        int r = cc >> 6, off = (cc & 63) * 8;
                        cp16(dst + r * 512 + off, src + (size_t)r * 512 + off);
                    }
                    CP_COMMIT();
                }
                for (int s = 0; s < 18; s++) {
                    cp_wait_dyn(17 - s < 3 ? 17 - s : 3);
                    __syncwarp();
                    const __half2* r0 = reinterpret_cast<const __half2*>(wpipe + (s & 3) * 1024);
                    const __half2* r1 = r0 + 256;
                    float a0 = 0.f, a1 = 0.f;
                    #pragma unroll
                    for (int k = 0; k < 2; k++) {
                        int d2 = lane * 4 + k * 128;
                        uint4 u0 = *reinterpret_cast<const uint4*>(r0 + d2);
                        uint4 u1 = *reinterpret_cast<const uint4*>(r1 + d2);
                        uint4 hu = *reinterpret_cast<const uint4*>(hU2s + d2);
                        uint4 vv = *reinterpret_cast<const uint4*>(vs2s + d2);
                        __half2 acc0 = __float2half2_rn(0.f);
                        __half2 acc1 = acc0;
                        #pragma unroll
                        for (int j = 0; j < 4; j++) {
                            __half2 hj = *reinterpret_cast<__half2*>(&(&hu.x)[j]);
                            __half2 vj = *reinterpret_cast<__half2*>(&(&vv.x)[j]);
                            __half2 w0 = *reinterpret_cast<__half2*>(&(&u0.x)[j]);
                            __half2 w1 = *reinterpret_cast<__half2*>(&(&u1.x)[j]);
                            acc0 = __hfma2(vj, tanh2(__hadd2(w0, hj)), acc0);
                            acc1 = __hfma2(vj, tanh2(__hadd2(w1, hj)), acc1);
                        }
                        float2 f0 = __half22float2(acc0);
                        float2 f1 = __half22float2(acc1);
                        a0 += f0.x + f0.y;
                        a1 += f1.x + f1.y;
                    }
                    #pragma unroll
                    for (int o = 16; o; o >>= 1) {
                        a0 += __shfl_down_sync(0xffffffffu, a0, o);
                        a1 += __shfl_down_sync(0xffffffffu, a1, o);
                    }
                    int p = wid * 2 + s * 32;
                    if (lane == 0) { es[p] = a0 + vb0; es[p + 1] = a1 + vb0; }
                    __syncwarp();
                    if (s + 4 < 18) {
                        int pn = wid * 2 + (s + 4) * 32;
                        const __half* src = wsb + (size_t)pn * 512;
                        __half* dst = wpipe + (s & 3) * 1024;
                        #pragma unroll
                        for (int q = 0; q < 4; q++) {
                            int cc = lane * 4 + q;
                            int r = cc >> 6, off = (cc & 63) * 8;
                            cp16(dst + r * 512 + off, src + (size_t)r * 512 + off);
                        }
                        CP_COMMIT();
                    }
                }
            }
            __syncthreads();
            // ---- softmax over 576 (warp-shuffle reductions, 4 syncthreads)
            float lmax = -1e30f;
            for (int p = tid; p < Pz; p += NTHR) lmax = fmaxf(lmax, es[p]);
            #pragma unroll
            for (int o = 16; o; o >>= 1)
                lmax = fmaxf(lmax, __shfl_xor_sync(0xffffffffu, lmax, o));
            if (lane == 0) red[wid] = lmax;
            __syncthreads();
            if (tid < 32) {
                float v = (tid < 16) ? red[tid] : -1e30f;
                #pragma unroll
                for (int o = 8; o; o >>= 1)
                    v = fmaxf(v, __shfl_xor_sync(0xffffffffu, v, o));
                if (tid == 0) red[16] = v;
            }
            __syncthreads();
            float mx = red[16];
            float ls = 0.f;
            for (int p = tid; p < Pz; p += NTHR) {
                float v = __expf(es[p] - mx);
                es[p] = v; ls += v;
            }
            #pragma unroll
            for (int o = 16; o; o >>= 1) ls += __shfl_xor_sync(0xffffffffu, ls, o);
            if (lane == 0) red[wid] = ls;
            __syncthreads();
            if (tid < 32) {
                float v = (tid < 16) ? red[tid] : 0.f;
                #pragma unroll
                for (int o = 8; o; o >>= 1) v += __shfl_xor_sync(0xffffffffu, v, o);
                if (tid == 0) red[17] = 1.0f / v;
            }
            __syncthreads();
            float inv = red[17];
            float msk = ((lengths[b] - 1) > t) ? 1.0f : 0.0f;
            for (int p = tid; p < Pz; p += NTHR) {
                float a = es[p] * inv;
                es[p] = a;
                alphas_out[((size_t)b * TM1 + t) * Pz + p] = a * msk;
            }
            __syncthreads();
            if (tid < 288)
                es2s[tid] = __floats2half2_rn(es[2 * tid], es[2 * tid + 1]);
            __syncthreads();
            // ================= ctx: 16 per-warp stages (2 e-rows each) =======
            {
                const __half* fhb = g_featsh + (size_t)b * EP;
                __half* wpipe = pipe + wid * 4608;   // 4 stages x 1152 halves
                #pragma unroll
                for (int s = 0; s < 4; s++) {
                    int e0 = wid * 2 + s * 32;
                    const __half* src = fhb + (size_t)e0 * Pz;
                    __half* dst = wpipe + (s & 3) * 1152;
                    #pragma unroll
                    for (int q = 0; q < 5; q++) {
                        int cc = lane + q * 32;      // 0..143 uint4
                        if (cc < 144) {
                            int r = cc / 72, off = (cc % 72) * 8;
                            cp16(dst + r * 576 + off, src + (size_t)r * Pz + off);
                        }
                    }
                    CP_COMMIT();
                }
                for (int s = 0; s < 16; s++) {
                    cp_wait_dyn(15 - s < 3 ? 15 - s : 3);
                    __syncwarp();
                    const __half2* r0 = reinterpret_cast<const __half2*>(wpipe + (s & 3) * 1152);
                    const __half2* r1 = r0 + 288;
                    float a0 = 0.f, a1 = 0.f;
                    #pragma unroll
                    for (int k = 0; k < 2; k++) {
                        int d2 = lane * 4 + k * 128;
                        uint4 u0 = *reinterpret_cast<const uint4*>(r0 + d2);
                        uint4 u1 = *reinterpret_cast<const uint4*>(r1 + d2);
                        uint4 ev = *reinterpret_cast<const uint4*>(es2s + d2);
                        __half2 acc0 = __float2half2_rn(0.f);
                        __half2 acc1 = acc0;
                        #pragma unroll
                        for (int j = 0; j < 4; j++) {
                            __half2 ej = *reinterpret_cast<__half2*>(&(&ev.x)[j]);
                            __half2 w0 = *reinterpret_cast<__half2*>(&(&u0.x)[j]);
                            __half2 w1 = *reinterpret_cast<__half2*>(&(&u1.x)[j]);
                            acc0 = __hfma2(w0, ej, acc0);
                            acc1 = __hfma2(w1, ej, acc1);
                        }
                        float2 f0 = __half22float2(acc0);
                        float2 f1 = __half22float2(acc1);
                        a0 += f0.x + f0.y;
                        a1 += f1.x + f1.y;
                    }
                    if (lane < 8) {                  // tail p = 512..575
                        int d2 = 256 + lane * 4;
                        uint4 u0 = *reinterpret_cast<const uint4*>(r0 + d2);
                        uint4 u1 = *reinterpret_cast<const uint4*>(r1 + d2);
                        uint4 ev = *reinterpret_cast<const uint4*>(es2s + d2);
                        __half2 acc0 = __float2half2_rn(0.f);
                        __half2 acc1 = acc0;
                        #pragma unroll
                        for (int j = 0; j < 4; j++) {
                            __half2 ej = *reinterpret_cast<__half2*>(&(&ev.x)[j]);
                            __half2 w0 = *reinterpret_cast<__half2*>(&(&u0.x)[j]);
                            __half2 w1 = *reinterpret_cast<__half2*>(&(&u1.x)[j]);
                            acc0 = __hfma2(w0, ej, acc0);
                            acc1 = __hfma2(w1, ej, acc1);
                        }
                        float2 f0 = __half22float2(acc0);
                        float2 f1 = __half22float2(acc1);
                        a0 += f0.x + f0.y;
                        a1 += f1.x + f1.y;
                    }
                    #pragma unroll
                    for (int o = 16; o; o >>= 1) {
                        a0 += __shfl_down_sync(0xffffffffu, a0, o);
                        a1 += __shfl_down_sync(0xffffffffu, a1, o);
                    }
                    int e = wid * 2 + s * 32;
                    if (lane == 0) {
                        float x0 = gs[e] * a0;
                        float x1 = gs[e + 1] * a1;
                        __half hi0 = __float2half_rn(x0);
                        __half hi1 = __float2half_rn(x1);
                        g_A2h_hi[b * 1024 + e]     = hi0;
                        g_A2h_hi[b * 1024 + e + 1] = hi1;
                        g_A2h_lo[b * 1024 + e]     = __float2half_rn(x0 - __half2float(hi0));
                        g_A2h_lo[b * 1024 + e + 1] = __float2half_rn(x1 - __half2float(hi1));
                    }
                    __syncwarp();
                    if (s + 4 < 16) {
                        int en = wid * 2 + (s + 4) * 32;
                        const __half* src = fhb + (size_t)en * Pz;
                        __half* dst = wpipe + (s & 3) * 1152;
                        #pragma unroll
                        for (int q = 0; q < 5; q++) {
                            int cc = lane + q * 32;
                            if (cc < 144) {
                                int r = cc / 72, off = (cc % 72) * 8;
                                cp16(dst + r * 576 + off, src + (size_t)r * Pz + off);
                            }
                        }
                        CP_COMMIT();
                    }
                }
            }
        }
        gridsync();

        // ------------- Phase D: mma hi/lo 3-term, double-buffered A (1 sync/tile)
        {
            __half* Bh = reinterpret_cast<__half*>(dyns);      // [16][1032]
            __half* Bl = Bh + 16512;                           // halves 16512..33024
            __half* Abase = Bl + 16512;                        // 2 stages x (Ah+Al)
            // stage s: Ah = Abase + s*18432, Al = Ah + 9216 (halves, row stride 72)
            int j0g = bx * 16;
            #pragma unroll
            for (int q = 0; q < 4; q++) {
                int cc = tid + q * 512;
                int j = cc >> 7, off = (cc & 127) * 8;
                *reinterpret_cast<uint4*>(Bh + j * 1032 + off) =
                    *reinterpret_cast<const uint4*>(g_W2h_hi + (size_t)(j0g + j) * 1024 + off);
                *reinterpret_cast<uint4*>(Bl + j * 1032 + off) =
                    *reinterpret_cast<const uint4*>(g_W2h_lo + (size_t)(j0g + j) * 1024 + off);
            }
            int cc0 = tid * 2, cc1 = tid * 2 + 1;
            int ar0 = cc0 >> 3, ao0 = (cc0 & 7) * 8;
            int ar1 = cc1 >> 3, ao1 = (cc1 & 7) * 8;
            uint4 pa0 = *reinterpret_cast<const uint4*>(g_A2h_hi + ar0 * 1024 + ao0);
            uint4 pa1 = *reinterpret_cast<const uint4*>(g_A2h_hi + ar1 * 1024 + ao1);
            uint4 pl0 = *reinterpret_cast<const uint4*>(g_A2h_lo + ar0 * 1024 + ao0);
            uint4 pl1 = *reinterpret_cast<const uint4*>(g_A2h_lo + ar1 * 1024 + ao1);
            int m0 = (wid >> 1) * 16, n0 = (wid & 1) * 8;
            float c0 = 0.f, c1 = 0.f, c2 = 0.f, c3 = 0.f;
            for (int tt = 0; tt < 16; tt++) {
                __half* Ah = Abase + (tt & 1) * 18432;
                __half* Al = Ah + 9216;
                *reinterpret_cast<uint4*>(Ah + ar0 * 72 + ao0) = pa0;
                *reinterpret_cast<uint4*>(Ah + ar1 * 72 + ao1) = pa1;
                *reinterpret_cast<uint4*>(Al + ar0 * 72 + ao0) = pl0;
                *reinterpret_cast<uint4*>(Al + ar1 * 72 + ao1) = pl1;
                __syncthreads();
                if (tt + 1 < 16) {
                    int k0n = (tt + 1) * 64;
                    pa0 = *reinterpret_cast<const uint4*>(g_A2h_hi + ar0 * 1024 + k0n + ao0);
                    pa1 = *reinterpret_cast<const uint4*>(g_A2h_hi + ar1 * 1024 + k0n + ao1);
                    pl0 = *reinterpret_cast<const uint4*>(g_A2h_lo + ar0 * 1024 + k0n + ao0);
                    pl1 = *reinterpret_cast<const uint4*>(g_A2h_lo + ar1 * 1024 + k0n + ao1);
                }
                int k0 = tt * 64;
                #pragma unroll
                for (int kin = 0; kin < 4; kin++) {
                    int kk = kin * 16;
                    unsigned a0, a1, a2, a3, l0, l1, l2, l3, b0, b1, q0, q1;
                    ldsm4(a0, a1, a2, a3,
                          Ah + (m0 + (lane & 15)) * 72 + kk + (lane >> 4) * 8);
                    ldsm4(l0, l1, l2, l3,
                          Al + (m0 + (lane & 15)) * 72 + kk + (lane >> 4) * 8);
                    ldsm2(b0, b1,
                          Bh + (n0 + (lane & 7)) * 1032 + k0 + kk + ((lane >> 3) & 1) * 8);
                    ldsm2(q0, q1,
                          Bl + (n0 + (lane & 7)) * 1032 + k0 + kk + ((lane >> 3) & 1) * 8);
                    mma16816(c0, c1, c2, c3, a0, a1, a2, a3, b0, b1);
                    mma16816(c0, c1, c2, c3, a0, a1, a2, a3, q0, q1);
                    mma16816(c0, c1, c2, c3, l0, l1, l2, l3, b0, b1);
                }
                // no trailing sync: next tile writes the OTHER stage buffer
            }
            int bb = m0 + (lane >> 2);
            int jj = j0g + n0 + (lane & 3) * 2;
            float2 v0 = {c0, c1};
            float2 v1 = {c2, c3};
            *reinterpret_cast<float2*>(&g_gate[bb * 2048 + jj]) = v0;
            *reinterpret_cast<float2*>(&g_gate[(bb + 8) * 2048 + jj]) = v1;
        }
        gridsync();

        // ------------- Phase E: gates + embW + LSTM cell + pred gemm
        {
            const int b = bx;
            float* h2s = smf;            // 512
            const float* cprev = g_c[cur];
            float* cnext = g_c[cur ^ 1];
            float* hnext = g_h[cur ^ 1];
            int cap = captions[b * Tz + t];
            const float* ew = g_embW + (size_t)cap * 2048;
            const float* gp = g_gate + b * 2048;
            {
                int d = tid;
                float gi = bih[d]        + bhh[d]        + ew[d]        + gp[d];
                float gf = bih[512 + d]  + bhh[512 + d]  + ew[512 + d]  + gp[512 + d];
                float gg = bih[1024 + d] + bhh[1024 + d] + ew[1024 + d] + gp[1024 + d];
                float go = bih[1536 + d] + bhh[1536 + d] + ew[1536 + d] + gp[1536 + d];
                float c2 = fast_sigmoid(gf) * cprev[b * 512 + d]
                         + fast_sigmoid(gi) * fast_tanh(gg);
                float h2 = fast_sigmoid(go) * fast_tanh(c2);
                cnext[b * 512 + d] = c2;
                hnext[b * 512 + d] = h2;
                __half hi = __float2half_rn(h2);
                g_A2h_hi[b * 1024 + 512 + d] = hi;
                g_A2h_lo[b * 1024 + 512 + d] = __float2half_rn(h2 - __half2float(hi));
                h2s[d] = h2;
            }
            __syncthreads();
            float msk = ((lengths[b] - 1) > t) ? 1.0f : 0.0f;
            if (tid < Vz) {
                int v = tid;
                const float* row = g_fcwT + v * 512;
                float a0 = 0.f, a1 = 0.f, a2 = 0.f, a3 = 0.f;
                #pragma unroll 8
                for (int d = 0; d < 512; d += 4) {
                    float4 w = *reinterpret_cast<const float4*>(row + d);
                    float4 hh = *reinterpret_cast<const float4*>(h2s + d);
                    a0 = fmaf(hh.x, w.x, a0);
                    a1 = fmaf(hh.y, w.y, a1);
                    a2 = fmaf(hh.z, w.z, a2);
                    a3 = fmaf(hh.w, w.w, a3);
                }
                float acc = fcb[v] + ((a0 + a1) + (a2 + a3));
                preds_out[((size_t)b * TM1 + t) * Vz + v] = acc * msk;
            }
            __syncthreads();
        }
        gridsync();
    }
}

// ---------------- launch ------------------------------------------------------
extern "C" void kernel_launch(void* const* d_in, const int* in_sizes, int n_in,
                              void* d_out, int out_size) {
    const float* feats    = (const float*)d_in[0];
    const int*   captions = (const int*)d_in[1];
    const int*   lengths  = (const int*)d_in[2];
    const float* U_w  = (const float*)d_in[3];
    const float* U_b  = (const float*)d_in[4];
    const float* W_w  = (const float*)d_in[5];
    const float* W_b  = (const float*)d_in[6];
    const float* v_w  = (const float*)d_in[7];
    const float* v_b  = (const float*)d_in[8];
    const float* ihw  = (const float*)d_in[9];
    const float* ihb  = (const float*)d_in[10];
    const float* icw  = (const float*)d_in[11];
    const float* icb  = (const float*)d_in[12];
    const float* fbw  = (const float*)d_in[13];
    const float* fbb  = (const float*)d_in[14];
    const float* fcw  = (const float*)d_in[15];
    const float* fcb  = (const float*)d_in[16];
    const float* emb  = (const float*)d_in[17];
    const float* wih  = (const float*)d_in[18];
    const float* whh  = (const float*)d_in[19];
    const float* bih  = (const float*)d_in[20];
    const float* bhh  = (const float*)d_in[21];

    float* out    = (float*)d_out;
    float* preds  = out;
    float* alphas = out + (size_t)Bz * TM1 * Vz;
    float* dec    = alphas + (size_t)Bz * TM1 * Pz;

    cudaFuncSetAttribute(decode_kernel,
                         cudaFuncAttributeMaxDynamicSharedMemorySize, DSMEM);

    prep_misc_kernel<<<17210, 256>>>(feats, fcw, emb, wih, whh, lengths, dec);
    prep2_kernel<<<18448, 256>>>(feats, ihw, icw, ihb, icb);
    ws_gemm_kernel<<<dim3(9, 8, Bz), 256>>>(feats, W_w, W_b);
    decode_kernel<<<GRID, NTHR, DSMEM>>>(U_w, U_b, v_w, v_b, fbw, fbb,
                                         captions, lengths,
                                         bih, bhh, fcb,
                                         preds, alphas);
    (void)in_sizes; (void)n_in; (void)out_size;
}